// round 6
// baseline (speedup 1.0000x reference)
#include <cuda_runtime.h>
#include <cuda_bf16.h>
#include <math.h>
#include <stdint.h>

#define Bv   2
#define Nv   2048
#define Mv   2048
#define Cv   512
#define Kv   16
#define K1v  8
#define KEYv 1024
#define H1v  64
#define H2v  128

// d_out layout: R[2,3,3] | tvec[2,3] | src_kp[2,3,1024] | tgt_kp[2,3,1024]
//             | src_kp_knn[2,3,1024,16] | tgt_kp_knn[2,3,1024,16] | loss
#define OFF_R    0
#define OFF_T    18
#define OFF_SK   24
#define OFF_TK   (24 + 6144)
#define OFF_SKK  (24 + 12288)
#define OFF_TKK  (24 + 12288 + 98304)
#define OFF_LOSS (24 + 12288 + 196608)

// ---------------- scratch (device globals; no allocation allowed) -----------
__device__ float g_dist[Bv * Nv * Mv];   // 33.5 MB
__device__ float g_e   [Bv * Nv * Mv];   // 33.5 MB  e = exp(-dist), unnormalized
__device__ float g_xx[Bv * Nv];
__device__ float g_yy[Bv * Mv];
__device__ float g_z [Bv * Nv];          // per-row sum of e (softmax denominator)
__device__ float g_scorr[Bv * 3 * Nv];
__device__ float g_maxp[Bv * Nv];
__device__ float g_s[Bv * Nv];
__device__ int   g_topi[Bv * KEYv];
__device__ float g_R[Bv * 9];
__device__ float g_tv[Bv * 3];
__device__ float g_res[Bv * 15];
// bf16 split embeddings, [b][n][0..511]=hi, [b][n][512..1023]=lo  (k-contig)
__device__ __align__(256) __nv_bfloat16 g_A2[Bv * Nv * 1024];
__device__ __align__(256) __nv_bfloat16 g_B2[Bv * Mv * 1024];

// =================== helpers ================================================
__device__ __forceinline__ uint32_t smem_to_u32(const void* p) {
    uint32_t a;
    asm("{ .reg .u64 t; cvta.to.shared.u64 t, %1; cvt.u32.u64 %0, t; }" : "=r"(a) : "l"(p));
    return a;
}
static __device__ __forceinline__ void cp_async16(uint32_t dst, const void* src) {
    asm volatile("cp.async.cg.shared.global [%0], [%1], 16;" :: "r"(dst), "l"(src) : "memory");
}
static __device__ __forceinline__ void ldm_x4(uint32_t* r, uint32_t addr) {
    asm volatile("ldmatrix.sync.aligned.m8n8.x4.shared.b16 {%0,%1,%2,%3}, [%4];"
                 : "=r"(r[0]), "=r"(r[1]), "=r"(r[2]), "=r"(r[3]) : "r"(addr));
}
static __device__ __forceinline__ void mma16816(float* c, const uint32_t* a,
                                                uint32_t b0, uint32_t b1) {
    asm volatile(
        "mma.sync.aligned.m16n8k16.row.col.f32.bf16.bf16.f32 "
        "{%0,%1,%2,%3},{%4,%5,%6,%7},{%8,%9},{%0,%1,%2,%3};"
        : "+f"(c[0]), "+f"(c[1]), "+f"(c[2]), "+f"(c[3])
        : "r"(a[0]), "r"(a[1]), "r"(a[2]), "r"(a[3]), "r"(b0), "r"(b1));
}

// ---------------- zero accumulators -----------------------------------------
__global__ void k_zero() {
    int i = blockIdx.x * 256 + threadIdx.x;
    g_xx[i] = 0.f;
    g_yy[i] = 0.f;
    g_z[i]  = 0.f;
}

// ------- fp32 -> bf16 hi/lo transpose-split + fused column sq-norms ---------
// grid.z: 0,1 -> semb batch 0,1 ; 2,3 -> temb batch 0,1
__global__ __launch_bounds__(256) void k_conv(const float* __restrict__ semb,
                                              const float* __restrict__ temb) {
    __shared__ float ts[32][33];
    __shared__ float colsum[32];
    int z = blockIdx.z;
    int which = z >> 1, b = z & 1;
    const float* e = which ? temb : semb;
    __nv_bfloat16* out = which ? g_B2 : g_A2;
    float* norm = which ? g_yy : g_xx;
    int c0 = blockIdx.y * 32, n0 = blockIdx.x * 32;
    int tx = threadIdx.x & 31, ty = threadIdx.x >> 5;
    if (threadIdx.x < 32) colsum[threadIdx.x] = 0.f;
    __syncthreads();
    float ps = 0.f;
    for (int i = ty; i < 32; i += 8) {
        float v = e[((size_t)b * Cv + c0 + i) * 2048 + n0 + tx];
        ts[i][tx] = v;
        ps = fmaf(v, v, ps);
    }
    atomicAdd(&colsum[tx], ps);
    __syncthreads();
    if (threadIdx.x < 32)
        atomicAdd(&norm[b * 2048 + n0 + threadIdx.x], colsum[threadIdx.x]);
    for (int i = ty; i < 32; i += 8) {
        float x = ts[tx][i];
        __nv_bfloat16 h = __float2bfloat16(x);
        __nv_bfloat16 l = __float2bfloat16(x - __bfloat162float(h));
        size_t base = ((size_t)b * 2048 + n0 + i) * 1024 + c0 + tx;
        out[base] = h;
        out[base + 512] = l;
    }
}

// ---------------- bf16 mma.sync GEMM + fused exp/rowsum epilogue ------------
// dist = xx - 2*A.B^T + yy ; e = exp(-dist) ; g_z[row] += sum(e)
// CTA tile 128(row=src n) x 128(col=tgt m); K'=1536 as 24 chunks of 64.
#define MM_SMEM (6 * 16384)

__global__ __launch_bounds__(256) void k_mm(float* __restrict__ dist,
                                            float* __restrict__ earr) {
    extern __shared__ char smem[];
    const uint32_t sbA = smem_to_u32(smem);            // 3 bufs x 128 rows x 128B
    const uint32_t sbB = sbA + 49152;                  // 3 bufs x 128 rows x 128B
    const int tid = threadIdx.x;
    const int lane = tid & 31, wid = tid >> 5;
    const int warp_m = (wid >> 1) * 32;   // row (src-n) offset in tile
    const int warp_n = (wid & 1) * 64;    // col (tgt-m) offset in tile
    const int bz = blockIdx.z;
    const int row0 = blockIdx.y * 128;    // src n
    const int col0 = blockIdx.x * 128;    // tgt m

    const char* Arow = (const char*)(g_A2 + ((size_t)bz * 2048 + row0) * 1024);
    const char* Brow = (const char*)(g_B2 + ((size_t)bz * 2048 + col0) * 1024);

    float c[2][8][4];
#pragma unroll
    for (int mt = 0; mt < 2; mt++)
#pragma unroll
        for (int nt = 0; nt < 8; nt++)
#pragma unroll
            for (int q = 0; q < 4; q++) c[mt][nt][q] = 0.f;

    auto load_chunk = [&](int it, int stage) {
        const int ab = ((it >= 16) ? 512 : 0) + (it & 7) * 64;
        const int bb = ((it >= 8 && it < 16) ? 512 : 0) + (it & 7) * 64;
        const char* ap = Arow + ab * 2;
        const char* bp = Brow + bb * 2;
        const uint32_t ad = sbA + stage * 16384;
        const uint32_t bd = sbB + stage * 16384;
#pragma unroll
        for (int u = 0; u < 4; u++) {
            int o = tid + u * 256;
            int r = o >> 3, s = o & 7;
            uint32_t sw = ((uint32_t)(s ^ (r & 7))) << 4;
            cp_async16(ad + r * 128 + sw, ap + (size_t)r * 2048 + s * 16);
            cp_async16(bd + r * 128 + sw, bp + (size_t)r * 2048 + s * 16);
        }
        asm volatile("cp.async.commit_group;" ::: "memory");
    };

    load_chunk(0, 0);
    load_chunk(1, 1);

    for (int it = 0; it < 24; it++) {
        if (it < 23) asm volatile("cp.async.wait_group 1;" ::: "memory");
        else         asm volatile("cp.async.wait_group 0;" ::: "memory");
        __syncthreads();
        if (it + 2 < 24) load_chunk(it + 2, (it + 2) % 3);

        const int buf = it % 3;
        const uint32_t aB = sbA + buf * 16384;
        const uint32_t bB = sbB + buf * 16384;
#pragma unroll
        for (int kk = 0; kk < 4; kk++) {
            uint32_t afr[2][4];
#pragma unroll
            for (int mt = 0; mt < 2; mt++) {
                int row = warp_m + mt * 16 + (lane & 7) + ((lane >> 3) & 1) * 8;
                int ch = 2 * kk + (lane >> 4);
                ldm_x4(afr[mt], aB + row * 128 + (((uint32_t)(ch ^ (row & 7))) << 4));
            }
            uint32_t bfr[4][4];
#pragma unroll
            for (int nt = 0; nt < 4; nt++) {
                int sel = lane >> 3;
                int row = warp_n + nt * 16 + (lane & 7) + (sel >> 1) * 8;
                int ch = 2 * kk + (sel & 1);
                ldm_x4(bfr[nt], bB + row * 128 + (((uint32_t)(ch ^ (row & 7))) << 4));
            }
#pragma unroll
            for (int mt = 0; mt < 2; mt++)
#pragma unroll
                for (int n8 = 0; n8 < 8; n8++)
                    mma16816(c[mt][n8], afr[mt],
                             bfr[n8 >> 1][(n8 & 1) * 2], bfr[n8 >> 1][(n8 & 1) * 2 + 1]);
        }
    }

    // epilogue: dist = xx - 2*acc + yy ; e = exp(-dist) ; row-sum -> g_z
    const int grp = lane >> 2, qp = lane & 3;
#pragma unroll
    for (int mt = 0; mt < 2; mt++) {
        int m = warp_m + mt * 16 + grp;
        float x0 = g_xx[bz * 2048 + row0 + m];
        float x1 = g_xx[bz * 2048 + row0 + m + 8];
        size_t ro = ((size_t)(bz * 2048 + row0 + m)) * 2048 + col0;
        float* d0 = dist + ro;
        float* d1 = d0 + (size_t)8 * 2048;
        float* e0p = earr + ro;
        float* e1p = e0p + (size_t)8 * 2048;
        float s0 = 0.f, s1 = 0.f;
#pragma unroll
        for (int n8 = 0; n8 < 8; n8++) {
            int n = warp_n + n8 * 8 + qp * 2;
            float y0 = g_yy[bz * 2048 + col0 + n];
            float y1 = g_yy[bz * 2048 + col0 + n + 1];
            float2 v0, v1;
            v0.x = fmaf(-2.f, c[mt][n8][0], x0 + y0);
            v0.y = fmaf(-2.f, c[mt][n8][1], x0 + y1);
            v1.x = fmaf(-2.f, c[mt][n8][2], x1 + y0);
            v1.y = fmaf(-2.f, c[mt][n8][3], x1 + y1);
            *(float2*)(d0 + n) = v0;
            *(float2*)(d1 + n) = v1;
            float2 w0, w1;
            w0.x = __expf(-v0.x); w0.y = __expf(-v0.y);
            w1.x = __expf(-v1.x); w1.y = __expf(-v1.y);
            *(float2*)(e0p + n) = w0;
            *(float2*)(e1p + n) = w1;
            s0 += w0.x + w0.y;
            s1 += w1.x + w1.y;
        }
        s0 += __shfl_xor_sync(~0u, s0, 1);
        s0 += __shfl_xor_sync(~0u, s0, 2);
        s1 += __shfl_xor_sync(~0u, s1, 1);
        s1 += __shfl_xor_sync(~0u, s1, 2);
        if (qp == 0) {
            atomicAdd(&g_z[bz * 2048 + row0 + m], s0);
            atomicAdd(&g_z[bz * 2048 + row0 + m + 8], s1);
        }
    }
}

// -------- fused: T gather-sum -> S -> refined -> rmm -> src_corr, maxprob ---
// 4 consecutive src-rows per block; scores[r,m] = e[r,m] / Z[r] (deferred).
#define RMM_SMEM (16384 * 4 + 256)

__global__ __launch_bounds__(256) void k_rmm(const int* __restrict__ idx1,
                                             const int* __restrict__ idx2,
                                             const float* __restrict__ tgt) {
    extern __shared__ float sm[];
    float* Trow = sm;              // [4][2048]
    float* rf   = sm + 8192;       // [4][2048]
    float* red  = sm + 16384;      // [8]
    float* bc   = sm + 16392;      // [4]
    int blk = blockIdx.x;
    int b = blk >> 9;
    int n0 = (blk & 511) * 4;
    int t = threadIdx.x, lane = t & 31, wid = t >> 5;

    // pass 1: build 4 T rows (gather 7 e-rows each, scaled by 1/Z)
    const float4* base = (const float4*)(g_e + (size_t)(b << 11) * Mv);
#pragma unroll
    for (int r = 0; r < 4; r++) {
        const int* ip = idx1 + (size_t)((b << 11) + n0 + r) * K1v;
        const float4* rp[7];
        float zz[7];
#pragma unroll
        for (int k = 0; k < 7; k++) {
            int idx = ip[k + 1];
            rp[k] = base + (size_t)idx * 512;
            zz[k] = 1.0f / g_z[(b << 11) + idx];
        }
        float4* Tv = (float4*)(Trow + r * 2048);
        for (int q = t; q < 512; q += 256) {
            float4 o = {0.f, 0.f, 0.f, 0.f};
#pragma unroll
            for (int k = 0; k < 7; k++) {
                float4 a = rp[k][q];
                o.x = fmaf(a.x, zz[k], o.x);
                o.y = fmaf(a.y, zz[k], o.y);
                o.z = fmaf(a.z, zz[k], o.z);
                o.w = fmaf(a.w, zz[k], o.w);
            }
            Tv[q] = o;
        }
    }
    __syncthreads();

    // pass 2: gather S via idx2 (shared across 4 rows), refined softmax numerators
    const float* dp0 = g_dist + (size_t)((b << 11) + n0) * Mv;
    const int4* i2 = (const int4*)(idx2 + (size_t)b * Mv * K1v);
    float zs[4] = {0.f, 0.f, 0.f, 0.f};
    float em[4] = {0.f, 0.f, 0.f, 0.f};
    for (int m = t; m < Mv; m += 256) {
        int4 lo = i2[m * 2], hi = i2[m * 2 + 1];
#pragma unroll
        for (int r = 0; r < 4; r++) {
            const float* T = Trow + r * 2048;
            float S = T[lo.y] + T[lo.z] + T[lo.w] +
                      T[hi.x] + T[hi.y] + T[hi.z] + T[hi.w];
            float wq = __expf(1.0f - S * (1.0f / 7.0f));
            float e = __expf(-wq * dp0[(size_t)r * Mv + m]);
            rf[r * 2048 + m] = e;
            zs[r] += e;
            em[r] = fmaxf(em[r], e);
        }
    }
#pragma unroll
    for (int r = 0; r < 4; r++) {
        float z = zs[r], mx = em[r];
#pragma unroll
        for (int o = 16; o; o >>= 1) {
            z += __shfl_xor_sync(~0u, z, o);
            mx = fmaxf(mx, __shfl_xor_sync(~0u, mx, o));
        }
        if (lane == 0) { red[wid] = z; }
        __syncthreads();
        if (t == 0) {
            float zt = 0.f;
#pragma unroll
            for (int i = 0; i < 8; i++) zt += red[i];
            bc[r] = 1.0f / zt;
        }
        __syncthreads();
        if (lane == 0) red[wid] = mx;
        __syncthreads();
        if (t == 0) {
            float mt2 = 0.f;
#pragma unroll
            for (int i = 0; i < 8; i++) mt2 = fmaxf(mt2, red[i]);
            g_maxp[(b << 11) + n0 + r] = mt2 * bc[r];
        }
        __syncthreads();
    }

    // pass 3: single sweep for all 4 rows' correspondence sums
    const float* t0 = tgt + (size_t)b * 3 * Mv;
    float acc[12];
#pragma unroll
    for (int i = 0; i < 12; i++) acc[i] = 0.f;
    for (int m = t; m < Mv; m += 256) {
        float v0 = t0[m], v1 = t0[Mv + m], v2 = t0[2 * Mv + m];
#pragma unroll
        for (int r = 0; r < 4; r++) {
            float p = rf[r * 2048 + m];
            acc[r * 3 + 0] = fmaf(v0, p, acc[r * 3 + 0]);
            acc[r * 3 + 1] = fmaf(v1, p, acc[r * 3 + 1]);
            acc[r * 3 + 2] = fmaf(v2, p, acc[r * 3 + 2]);
        }
    }
#pragma unroll
    for (int i = 0; i < 12; i++) {
        float v = acc[i];
#pragma unroll
        for (int o = 16; o; o >>= 1) v += __shfl_xor_sync(~0u, v, o);
        if (lane == 0) red[wid] = v;
        __syncthreads();
        if (t == 0) {
            float s = 0.f;
#pragma unroll
            for (int j = 0; j < 8; j++) s += red[j];
            int r = i / 3, cc = i % 3;
            g_scorr[(b * 3 + cc) * Nv + n0 + r] = s * bc[r];
        }
        __syncthreads();
    }
}

// ---------------- discriminator MLP + max over k ----------------------------
__global__ __launch_bounds__(256) void k_disc(const float* __restrict__ src,
                                              const float* __restrict__ src_knn,
                                              const int* __restrict__ src_idx,
                                              const float* __restrict__ W1, const float* __restrict__ b1,
                                              const float* __restrict__ W2, const float* __restrict__ b2,
                                              const float* __restrict__ W3, const float* __restrict__ b3) {
    __shared__ float sW1[H1v * 6], sb1[H1v], sW2[H2v * H1v], sb2[H2v], sW3[H2v];
    __shared__ float sb3s;
    int t = threadIdx.x;
    for (int i = t; i < H1v * 6; i += 256) sW1[i] = W1[i];
    for (int i = t; i < H1v; i += 256) sb1[i] = b1[i];
    for (int i = t; i < H2v * H1v; i += 256) sW2[i] = W2[i];
    for (int i = t; i < H2v; i += 256) { sb2[i] = b2[i]; sW3[i] = W3[i]; }
    if (t == 0) sb3s = b3[0];
    __syncthreads();

    int gid = blockIdx.x * 256 + t;
    int k = gid & (Kv - 1);
    int n = (gid >> 4) & (Nv - 1);
    int b = gid >> 15;
    int j = src_idx[(size_t)gid];
    float f[6];
#pragma unroll
    for (int c = 0; c < 3; c++) {
        f[c]     = g_scorr[(b * 3 + c) * Nv + n] - g_scorr[(b * 3 + c) * Nv + j];
        f[3 + c] = src[(size_t)(b * 3 + c) * Nv + n] - src_knn[(size_t)gid * 3 + c];
    }
    float h1[H1v];
#pragma unroll
    for (int d = 0; d < H1v; d++) {
        float a = sb1[d];
#pragma unroll
        for (int c = 0; c < 6; c++) a = fmaf(sW1[d * 6 + c], f[c], a);
        h1[d] = fmaxf(a, 0.f);
    }
    float s = sb3s;
    const float4* W2v = (const float4*)sW2;
    for (int e = 0; e < H2v; e++) {
        float a = sb2[e];
#pragma unroll
        for (int dq = 0; dq < 16; dq++) {
            float4 w = W2v[e * 16 + dq];
            a = fmaf(w.x, h1[dq * 4 + 0], a);
            a = fmaf(w.y, h1[dq * 4 + 1], a);
            a = fmaf(w.z, h1[dq * 4 + 2], a);
            a = fmaf(w.w, h1[dq * 4 + 3], a);
        }
        s = fmaf(sW3[e], fmaxf(a, 0.f), s);
    }
#pragma unroll
    for (int off = 8; off > 0; off >>= 1)
        s = fmaxf(s, __shfl_xor_sync(0xffffffffu, s, off, 16));
    if (k == 0) g_s[(b << 11) + n] = s;
}

// ------- fused: weight softmax + rigid sums + exact top-k (per batch) -------
__global__ __launch_bounds__(1024) void k_post(const float* __restrict__ src) {
    int b = blockIdx.x; int t = threadIdx.x;
    int lane = t & 31, wid = t >> 5;
    __shared__ float sv[2048];
    __shared__ int   si[2048];
    __shared__ float red32[32];
    __shared__ float bcast;
    const float* s = g_s + b * Nv;
    float v0 = s[t], v1 = s[t + 1024];
    float mx = fmaxf(v0, v1);
#pragma unroll
    for (int o = 16; o; o >>= 1) mx = fmaxf(mx, __shfl_xor_sync(~0u, mx, o));
    if (lane == 0) red32[wid] = mx;
    __syncthreads();
    if (wid == 0) {
        float m = red32[lane];
#pragma unroll
        for (int o = 16; o; o >>= 1) m = fmaxf(m, __shfl_xor_sync(~0u, m, o));
        if (lane == 0) bcast = m;
    }
    __syncthreads();
    mx = bcast;
    float e0 = __expf(v0 - mx), e1 = __expf(v1 - mx);
    float zs = e0 + e1;
#pragma unroll
    for (int o = 16; o; o >>= 1) zs += __shfl_xor_sync(~0u, zs, o);
    if (lane == 0) red32[wid] = zs;
    __syncthreads();
    if (wid == 0) {
        float z = red32[lane];
#pragma unroll
        for (int o = 16; o; o >>= 1) z += __shfl_xor_sync(~0u, z, o);
        if (lane == 0) bcast = z;
    }
    __syncthreads();
    float inv = 1.0f / bcast;
    float w0 = e0 * inv, w1 = e1 * inv;
    sv[t] = w0;          si[t] = t;
    sv[t + 1024] = w1;   si[t + 1024] = t + 1024;

    const float* sx = src + (size_t)b * 3 * Nv;
    const float* cx = g_scorr + (size_t)b * 3 * Nv;
    float a[15];
    {
        int n1 = t, n2 = t + 1024;
        float s10 = sx[n1], s11 = sx[Nv + n1], s12 = sx[2 * Nv + n1];
        float c10 = cx[n1], c11 = cx[Nv + n1], c12 = cx[2 * Nv + n1];
        float s20 = sx[n2], s21 = sx[Nv + n2], s22 = sx[2 * Nv + n2];
        float c20 = cx[n2], c21 = cx[Nv + n2], c22 = cx[2 * Nv + n2];
        a[0] = w0 * s10 + w1 * s20;
        a[1] = w0 * s11 + w1 * s21;
        a[2] = w0 * s12 + w1 * s22;
        a[3] = w0 * c10 + w1 * c20;
        a[4] = w0 * c11 + w1 * c21;
        a[5] = w0 * c12 + w1 * c22;
        a[6]  = w0 * s10 * c10 + w1 * s20 * c20;
        a[7]  = w0 * s10 * c11 + w1 * s20 * c21;
        a[8]  = w0 * s10 * c12 + w1 * s20 * c22;
        a[9]  = w0 * s11 * c10 + w1 * s21 * c20;
        a[10] = w0 * s11 * c11 + w1 * s21 * c21;
        a[11] = w0 * s11 * c12 + w1 * s21 * c22;
        a[12] = w0 * s12 * c10 + w1 * s22 * c20;
        a[13] = w0 * s12 * c11 + w1 * s22 * c21;
        a[14] = w0 * s12 * c12 + w1 * s22 * c22;
    }
#pragma unroll
    for (int r = 0; r < 15; r++) {
        float val = a[r];
#pragma unroll
        for (int o = 16; o; o >>= 1) val += __shfl_xor_sync(~0u, val, o);
        if (lane == 0) red32[wid] = val;
        __syncthreads();
        if (wid == 0) {
            float v = red32[lane];
#pragma unroll
            for (int o = 16; o; o >>= 1) v += __shfl_xor_sync(~0u, v, o);
            if (lane == 0) g_res[b * 15 + r] = v;
        }
        __syncthreads();
    }

    for (int kk = 2; kk <= 2048; kk <<= 1) {
        for (int j = kk >> 1; j > 0; j >>= 1) {
            int i = t;
            int ixj = i ^ j;
            if (ixj > i) {
                float av = sv[i], bvv = sv[ixj];
                int ai = si[i], bi = si[ixj];
                bool aFirst = (av > bvv) || (av == bvv && ai < bi);
                bool desc = ((i & kk) == 0);
                if (desc != aFirst) {
                    sv[i] = bvv; si[i] = bi;
                    sv[ixj] = av; si[ixj] = ai;
                }
            }
            i = t + 1024;
            ixj = i ^ j;
            if (ixj > i) {
                float av = sv[i], bvv = sv[ixj];
                int ai = si[i], bi = si[ixj];
                bool aFirst = (av > bvv) || (av == bvv && ai < bi);
                bool desc = ((i & kk) == 0);
                if (desc != aFirst) {
                    sv[i] = bvv; si[i] = bi;
                    sv[ixj] = av; si[ixj] = ai;
                }
            }
            __syncthreads();
        }
    }
    g_topi[b * KEYv + t] = si[t];
}

// ---------------- 3x3 helpers ------------------------------------------------
__device__ double det3(const double M[3][3]) {
    return M[0][0] * (M[1][1] * M[2][2] - M[1][2] * M[2][1])
         - M[0][1] * (M[1][0] * M[2][2] - M[1][2] * M[2][0])
         + M[0][2] * (M[1][0] * M[2][1] - M[1][1] * M[2][0]);
}

__device__ void kabsch_R(const double H[3][3], double R[3][3]) {
    double A[3][3], V[3][3];
    for (int i = 0; i < 3; i++)
        for (int j = 0; j < 3; j++) {
            A[i][j] = H[0][i] * H[0][j] + H[1][i] * H[1][j] + H[2][i] * H[2][j];
            V[i][j] = (i == j) ? 1.0 : 0.0;
        }
    for (int sweep = 0; sweep < 12; sweep++) {
        double off = fabs(A[0][1]) + fabs(A[0][2]) + fabs(A[1][2]);
        if (off == 0.0) break;
        const int PQ[3][2] = {{0, 1}, {0, 2}, {1, 2}};
        for (int pi = 0; pi < 3; pi++) {
            int p = PQ[pi][0], q = PQ[pi][1];
            double apq = A[p][q];
            if (fabs(apq) < 1e-300) continue;
            double app = A[p][p], aqq = A[q][q];
            double tau = (aqq - app) / (2.0 * apq);
            double tt = (tau >= 0.0 ? 1.0 : -1.0) / (fabs(tau) + sqrt(1.0 + tau * tau));
            double cc = 1.0 / sqrt(1.0 + tt * tt);
            double ss = tt * cc;
            A[p][p] = app - tt * apq; A[q][q] = aqq + tt * apq;
            A[p][q] = 0.0; A[q][p] = 0.0;
            int r = 3 - p - q;
            double arp = A[r][p], arq = A[r][q];
            A[r][p] = cc * arp - ss * arq; A[p][r] = A[r][p];
            A[r][q] = ss * arp + cc * arq; A[q][r] = A[r][q];
            for (int i = 0; i < 3; i++) {
                double vp = V[i][p], vq = V[i][q];
                V[i][p] = cc * vp - ss * vq;
                V[i][q] = ss * vp + cc * vq;
            }
        }
    }
    double lam[3] = {A[0][0], A[1][1], A[2][2]};
    int ord[3] = {0, 1, 2};
    if (lam[ord[0]] < lam[ord[1]]) { int tmp = ord[0]; ord[0] = ord[1]; ord[1] = tmp; }
    if (lam[ord[0]] < lam[ord[2]]) { int tmp = ord[0]; ord[0] = ord[2]; ord[2] = tmp; }
    if (lam[ord[1]] < lam[ord[2]]) { int tmp = ord[1]; ord[1] = ord[2]; ord[2] = tmp; }
    double Vs[3][3], S[3], U[3][3];
    for (int k = 0; k < 3; k++) {
        int o = ord[k];
        S[k] = sqrt(fmax(lam[o], 0.0));
        for (int i = 0; i < 3; i++) Vs[i][k] = V[i][o];
    }
    for (int k = 0; k < 3; k++) {
        if (S[k] > 1e-12) {
            double inv = 1.0 / S[k];
            for (int i = 0; i < 3; i++)
                U[i][k] = (H[i][0] * Vs[0][k] + H[i][1] * Vs[1][k] + H[i][2] * Vs[2][k]) * inv;
        } else {
            U[0][k] = U[1][0] * U[2][1] - U[2][0] * U[1][1];
            U[1][k] = U[2][0] * U[0][1] - U[0][0] * U[2][1];
            U[2][k] = U[0][0] * U[1][1] - U[1][0] * U[0][1];
        }
    }
    double d = det3(U) * det3(Vs);
    for (int i = 0; i < 3; i++)
        for (int j = 0; j < 3; j++)
            R[i][j] = Vs[i][0] * U[j][0] + Vs[i][1] * U[j][1] + d * Vs[i][2] * U[j][2];
}

// ---------------- SVD / rigid transform (1 thread per batch) ----------------
__global__ void k_svd(float* __restrict__ out) {
    int b = blockIdx.x;
    if (threadIdx.x != 0) return;
    const float* res = g_res + b * 15;
    double cs[3] = {res[0], res[1], res[2]};
    double ct[3] = {res[3], res[4], res[5]};
    double H[3][3];
    for (int i = 0; i < 3; i++)
        for (int j = 0; j < 3; j++)
            H[i][j] = (double)res[6 + i * 3 + j] - cs[i] * ct[j];
    double R[3][3];
    kabsch_R(H, R);
    double tv[3];
    for (int i = 0; i < 3; i++)
        tv[i] = ct[i] - (R[i][0] * cs[0] + R[i][1] * cs[1] + R[i][2] * cs[2]);
    for (int i = 0; i < 3; i++)
        for (int j = 0; j < 3; j++) {
            out[OFF_R + b * 9 + i * 3 + j] = (float)R[i][j];
            g_R[b * 9 + i * 3 + j] = (float)R[i][j];
        }
    for (int i = 0; i < 3; i++) {
        out[OFF_T + b * 3 + i] = (float)tv[i];
        g_tv[b * 3 + i] = (float)tv[i];
    }
}

// ---------------- keypoint outputs (transform inline) -----------------------
__global__ void k_out(const float* __restrict__ src, const int* __restrict__ src_idx,
                      float* __restrict__ out) {
    int gid = blockIdx.x * 256 + threadIdx.x;
    int k = gid & (Kv - 1);
    int jj = (gid >> 4) & (KEYv - 1);
    int b = gid >> 14;
    const float* R = g_R + b * 9;
    float R00 = R[0], R01 = R[1], R02 = R[2];
    float R10 = R[3], R11 = R[4], R12 = R[5];
    float R20 = R[6], R21 = R[7], R22 = R[8];
    int n = g_topi[b * KEYv + jj];
    int m = src_idx[((size_t)(b * Nv) + n) * Kv + k];
    const float* sb = src + (size_t)b * 3 * Nv;
    const float* cb = g_scorr + (size_t)b * 3 * Nv;
    float sn0 = sb[n], sn1 = sb[Nv + n], sn2 = sb[2 * Nv + n];
    float sm0 = sb[m], sm1 = sb[Nv + m], sm2 = sb[2 * Nv + m];
    float d0 = sn0 - sm0, d1 = sn1 - sm1, d2 = sn2 - sm2;
    float sk0 = R00 * d0 + R01 * d1 + R02 * d2;
    float sk1 = R10 * d0 + R11 * d1 + R12 * d2;
    float sk2 = R20 * d0 + R21 * d1 + R22 * d2;
    size_t o0 = ((size_t)(b * 3 + 0) * KEYv + jj) * Kv + k;
    size_t o1 = ((size_t)(b * 3 + 1) * KEYv + jj) * Kv + k;
    size_t o2 = ((size_t)(b * 3 + 2) * KEYv + jj) * Kv + k;
    out[OFF_SKK + o0] = sk0;
    out[OFF_SKK + o1] = sk1;
    out[OFF_SKK + o2] = sk2;
    float cn0 = cb[n], cn1 = cb[Nv + n], cn2 = cb[2 * Nv + n];
    out[OFF_TKK + o0] = cn0 - cb[m];
    out[OFF_TKK + o1] = cn1 - cb[Nv + m];
    out[OFF_TKK + o2] = cn2 - cb[2 * Nv + m];
    if (k == 0) {
        out[OFF_SK + (size_t)(b * 3 + 0) * KEYv + jj] = sn0;
        out[OFF_SK + (size_t)(b * 3 + 1) * KEYv + jj] = sn1;
        out[OFF_SK + (size_t)(b * 3 + 2) * KEYv + jj] = sn2;
        out[OFF_TK + (size_t)(b * 3 + 0) * KEYv + jj] = cn0;
        out[OFF_TK + (size_t)(b * 3 + 1) * KEYv + jj] = cn1;
        out[OFF_TK + (size_t)(b * 3 + 2) * KEYv + jj] = cn2;
    }
}

// ---------------- loss -------------------------------------------------------
__global__ __launch_bounds__(1024) void k_loss(float* __restrict__ out) {
    __shared__ float red[1024];
    int t = threadIdx.x;
    float acc = 0.f;
    for (int idx = t; idx < Bv * KEYv; idx += 1024) {
        int b = idx >> 10;
        int n = g_topi[idx];
        acc += -__logf(g_maxp[b * Nv + n] + 1e-15f);
    }
    red[t] = acc; __syncthreads();
    for (int st = 512; st > 0; st >>= 1) { if (t < st) red[t] += red[t + st]; __syncthreads(); }
    if (t == 0) out[OFF_LOSS] = red[0] * (1.0f / (Bv * KEYv));
}

// ---------------- launch -----------------------------------------------------
extern "C" void kernel_launch(void* const* d_in, const int* in_sizes, int n_in,
                              void* d_out, int out_size) {
    const float* src   = (const float*)d_in[0];
    const float* tgt   = (const float*)d_in[1];
    const float* semb  = (const float*)d_in[2];
    const float* temb  = (const float*)d_in[3];
    const float* sknn  = (const float*)d_in[4];
    const float* W1    = (const float*)d_in[6];
    const float* b1    = (const float*)d_in[7];
    const float* W2    = (const float*)d_in[8];
    const float* b2    = (const float*)d_in[9];
    const float* W3    = (const float*)d_in[10];
    const float* b3    = (const float*)d_in[11];
    const int*   sidx  = (const int*)d_in[12];
    const int*   sidx1 = (const int*)d_in[13];
    const int*   idx2  = (const int*)d_in[14];
    float* out = (float*)d_out;

    cudaFuncSetAttribute(k_mm, cudaFuncAttributeMaxDynamicSharedMemorySize, MM_SMEM);
    cudaFuncSetAttribute(k_rmm, cudaFuncAttributeMaxDynamicSharedMemorySize, RMM_SMEM);

    float* distp;
    float* ep;
    cudaGetSymbolAddress((void**)&distp, g_dist);
    cudaGetSymbolAddress((void**)&ep, g_e);

    k_zero<<<16, 256>>>();
    dim3 cg(64, 16, 4);
    k_conv<<<cg, 256>>>(semb, temb);
    dim3 gg(Mv / 128, Nv / 128, Bv);
    k_mm<<<gg, 256, MM_SMEM>>>(distp, ep);
    k_rmm<<<Bv * Nv / 4, 256, RMM_SMEM>>>(sidx1, idx2, tgt);
    k_disc<<<(Bv * Nv * Kv) / 256, 256>>>(src, sknn, sidx, W1, b1, W2, b2, W3, b3);
    k_post<<<Bv, 1024>>>(src);
    k_svd<<<Bv, 1>>>(out);
    k_out<<<(Bv * KEYv * Kv) / 256, 256>>>(src, sidx, out);
    k_loss<<<1, 1024>>>(out);
}

// round 7
// speedup vs baseline: 1.7810x; 1.7810x over previous
#include <cuda_runtime.h>
#include <cuda_bf16.h>
#include <math.h>
#include <stdint.h>

#define Bv   2
#define Nv   2048
#define Mv   2048
#define Cv   512
#define Kv   16
#define K1v  8
#define KEYv 1024
#define H1v  64
#define H2v  128

// d_out layout: R[2,3,3] | tvec[2,3] | src_kp[2,3,1024] | tgt_kp[2,3,1024]
//             | src_kp_knn[2,3,1024,16] | tgt_kp_knn[2,3,1024,16] | loss
#define OFF_R    0
#define OFF_T    18
#define OFF_SK   24
#define OFF_TK   (24 + 6144)
#define OFF_SKK  (24 + 12288)
#define OFF_TKK  (24 + 12288 + 98304)
#define OFF_LOSS (24 + 12288 + 196608)

// ---------------- scratch (device globals; no allocation allowed) -----------
__device__ float g_dist[Bv * Nv * Mv];   // 33.5 MB
__device__ float g_sc  [Bv * Nv * Mv];   // 33.5 MB  scores = softmax(-dist)
__device__ float g_xx[Bv * Nv];
__device__ float g_yy[Bv * Mv];
__device__ float g_z [Bv * Nv];
__device__ float g_scorr[Bv * 3 * Nv];
__device__ float g_maxp[Bv * Nv];
__device__ float g_s[Bv * Nv];
__device__ int   g_topi[Bv * KEYv];
__device__ float g_R[Bv * 9];
__device__ float g_tv[Bv * 3];
__device__ float g_res[Bv * 15];
// bf16 split embeddings, [b][n][0..511]=hi, [b][n][512..1023]=lo  (k-contig)
__device__ __align__(256) __nv_bfloat16 g_A2[Bv * Nv * 1024];
__device__ __align__(256) __nv_bfloat16 g_B2[Bv * Mv * 1024];

// =================== helpers ================================================
__device__ __forceinline__ uint32_t smem_to_u32(const void* p) {
    uint32_t a;
    asm("{ .reg .u64 t; cvta.to.shared.u64 t, %1; cvt.u32.u64 %0, t; }" : "=r"(a) : "l"(p));
    return a;
}
static __device__ __forceinline__ void cp_async16(uint32_t dst, const void* src) {
    asm volatile("cp.async.cg.shared.global [%0], [%1], 16;" :: "r"(dst), "l"(src) : "memory");
}
static __device__ __forceinline__ void ldm_x4(uint32_t* r, uint32_t addr) {
    asm volatile("ldmatrix.sync.aligned.m8n8.x4.shared.b16 {%0,%1,%2,%3}, [%4];"
                 : "=r"(r[0]), "=r"(r[1]), "=r"(r[2]), "=r"(r[3]) : "r"(addr));
}
static __device__ __forceinline__ void mma16816(float* c, const uint32_t* a,
                                                uint32_t b0, uint32_t b1) {
    asm volatile(
        "mma.sync.aligned.m16n8k16.row.col.f32.bf16.bf16.f32 "
        "{%0,%1,%2,%3},{%4,%5,%6,%7},{%8,%9},{%0,%1,%2,%3};"
        : "+f"(c[0]), "+f"(c[1]), "+f"(c[2]), "+f"(c[3])
        : "r"(a[0]), "r"(a[1]), "r"(a[2]), "r"(a[3]), "r"(b0), "r"(b1));
}

// ---------------- zero accumulators -----------------------------------------
__global__ void k_zero() {
    int i = blockIdx.x * 256 + threadIdx.x;
    g_xx[i] = 0.f;
    g_yy[i] = 0.f;
    g_z[i]  = 0.f;
}

// ------- fp32 -> bf16 hi/lo transpose-split + fused column sq-norms ---------
__global__ __launch_bounds__(256) void k_conv(const float* __restrict__ e,
                                              __nv_bfloat16* __restrict__ out,
                                              float* __restrict__ norm) {
    __shared__ float ts[32][33];
    __shared__ float colsum[32];
    int b = blockIdx.z, c0 = blockIdx.y * 32, n0 = blockIdx.x * 32;
    int tx = threadIdx.x & 31, ty = threadIdx.x >> 5;
    if (threadIdx.x < 32) colsum[threadIdx.x] = 0.f;
    __syncthreads();
    float ps = 0.f;
    for (int i = ty; i < 32; i += 8) {
        float v = e[((size_t)b * Cv + c0 + i) * 2048 + n0 + tx];
        ts[i][tx] = v;
        ps = fmaf(v, v, ps);
    }
    atomicAdd(&colsum[tx], ps);
    __syncthreads();
    if (threadIdx.x < 32)
        atomicAdd(&norm[b * 2048 + n0 + threadIdx.x], colsum[threadIdx.x]);
    for (int i = ty; i < 32; i += 8) {
        float x = ts[tx][i];
        __nv_bfloat16 h = __float2bfloat16(x);
        __nv_bfloat16 l = __float2bfloat16(x - __bfloat162float(h));
        size_t base = ((size_t)b * 2048 + n0 + i) * 1024 + c0 + tx;
        out[base] = h;
        out[base + 512] = l;
    }
}

// ---------------- bf16 mma.sync GEMM: dist = xx - 2*A.B^T + yy --------------
// CTA tile 128(row=src n) x 128(col=tgt m); K'=1536 as 24 chunks of 64.
#define MM_SMEM (6 * 16384)

__global__ __launch_bounds__(256) void k_mm(float* __restrict__ dist) {
    extern __shared__ char smem[];
    const uint32_t sbA = smem_to_u32(smem);            // 3 bufs x 128 rows x 128B
    const uint32_t sbB = sbA + 49152;                  // 3 bufs x 128 rows x 128B
    const int tid = threadIdx.x;
    const int lane = tid & 31, wid = tid >> 5;
    const int warp_m = (wid >> 1) * 32;
    const int warp_n = (wid & 1) * 64;
    const int bz = blockIdx.z;
    const int row0 = blockIdx.y * 128;
    const int col0 = blockIdx.x * 128;

    const char* Arow = (const char*)(g_A2 + ((size_t)bz * 2048 + row0) * 1024);
    const char* Brow = (const char*)(g_B2 + ((size_t)bz * 2048 + col0) * 1024);

    float c[2][8][4];
#pragma unroll
    for (int mt = 0; mt < 2; mt++)
#pragma unroll
        for (int nt = 0; nt < 8; nt++)
#pragma unroll
            for (int q = 0; q < 4; q++) c[mt][nt][q] = 0.f;

    auto load_chunk = [&](int it, int stage) {
        const int ab = ((it >= 16) ? 512 : 0) + (it & 7) * 64;
        const int bb = ((it >= 8 && it < 16) ? 512 : 0) + (it & 7) * 64;
        const char* ap = Arow + ab * 2;
        const char* bp = Brow + bb * 2;
        const uint32_t ad = sbA + stage * 16384;
        const uint32_t bd = sbB + stage * 16384;
#pragma unroll
        for (int u = 0; u < 4; u++) {
            int o = tid + u * 256;
            int r = o >> 3, s = o & 7;
            uint32_t sw = ((uint32_t)(s ^ (r & 7))) << 4;
            cp_async16(ad + r * 128 + sw, ap + (size_t)r * 2048 + s * 16);
            cp_async16(bd + r * 128 + sw, bp + (size_t)r * 2048 + s * 16);
        }
        asm volatile("cp.async.commit_group;" ::: "memory");
    };

    load_chunk(0, 0);
    load_chunk(1, 1);

    for (int it = 0; it < 24; it++) {
        if (it < 23) asm volatile("cp.async.wait_group 1;" ::: "memory");
        else         asm volatile("cp.async.wait_group 0;" ::: "memory");
        __syncthreads();
        if (it + 2 < 24) load_chunk(it + 2, (it + 2) % 3);

        const int buf = it % 3;
        const uint32_t aB = sbA + buf * 16384;
        const uint32_t bB = sbB + buf * 16384;
#pragma unroll
        for (int kk = 0; kk < 4; kk++) {
            uint32_t afr[2][4];
#pragma unroll
            for (int mt = 0; mt < 2; mt++) {
                int row = warp_m + mt * 16 + (lane & 7) + ((lane >> 3) & 1) * 8;
                int ch = 2 * kk + (lane >> 4);
                ldm_x4(afr[mt], aB + row * 128 + (((uint32_t)(ch ^ (row & 7))) << 4));
            }
            uint32_t bfr[4][4];
#pragma unroll
            for (int nt = 0; nt < 4; nt++) {
                int sel = lane >> 3;
                int row = warp_n + nt * 16 + (lane & 7) + (sel >> 1) * 8;
                int ch = 2 * kk + (sel & 1);
                ldm_x4(bfr[nt], bB + row * 128 + (((uint32_t)(ch ^ (row & 7))) << 4));
            }
#pragma unroll
            for (int mt = 0; mt < 2; mt++)
#pragma unroll
                for (int n8 = 0; n8 < 8; n8++)
                    mma16816(c[mt][n8], afr[mt],
                             bfr[n8 >> 1][(n8 & 1) * 2], bfr[n8 >> 1][(n8 & 1) * 2 + 1]);
        }
    }

    const int grp = lane >> 2, qp = lane & 3;
#pragma unroll
    for (int mt = 0; mt < 2; mt++) {
        int m = warp_m + mt * 16 + grp;
        float x0 = g_xx[bz * 2048 + row0 + m];
        float x1 = g_xx[bz * 2048 + row0 + m + 8];
        float* d0 = dist + ((size_t)(bz * 2048 + row0 + m)) * 2048 + col0;
        float* d1 = d0 + (size_t)8 * 2048;
#pragma unroll
        for (int n8 = 0; n8 < 8; n8++) {
            int n = warp_n + n8 * 8 + qp * 2;
            float y0 = g_yy[bz * 2048 + col0 + n];
            float y1 = g_yy[bz * 2048 + col0 + n + 1];
            float2 v0, v1;
            v0.x = fmaf(-2.f, c[mt][n8][0], x0 + y0);
            v0.y = fmaf(-2.f, c[mt][n8][1], x0 + y1);
            v1.x = fmaf(-2.f, c[mt][n8][2], x1 + y0);
            v1.y = fmaf(-2.f, c[mt][n8][3], x1 + y1);
            *(float2*)(d0 + n) = v0;
            *(float2*)(d1 + n) = v1;
        }
    }
}

// ---------------- scores = softmax(-dist) row-wise (single pass) ------------
__global__ __launch_bounds__(256) void k_scores() {
    int row = blockIdx.x;
    const float4* d = (const float4*)(g_dist + (size_t)row * Mv);
    float4* sc = (float4*)(g_sc + (size_t)row * Mv);
    __shared__ float red[8];
    __shared__ float bc;
    int t = threadIdx.x, lane = t & 31, wid = t >> 5;
    float4 v0 = d[t], v1 = d[t + 256];
    float4 e0, e1;
    e0.x = __expf(-v0.x); e0.y = __expf(-v0.y); e0.z = __expf(-v0.z); e0.w = __expf(-v0.w);
    e1.x = __expf(-v1.x); e1.y = __expf(-v1.y); e1.z = __expf(-v1.z); e1.w = __expf(-v1.w);
    float zs = (e0.x + e0.y) + (e0.z + e0.w) + (e1.x + e1.y) + (e1.z + e1.w);
#pragma unroll
    for (int o = 16; o; o >>= 1) zs += __shfl_xor_sync(~0u, zs, o);
    if (lane == 0) red[wid] = zs;
    __syncthreads();
    if (t == 0) {
        float z = 0.f;
#pragma unroll
        for (int i = 0; i < 8; i++) z += red[i];
        bc = 1.0f / z;
    }
    __syncthreads();
    float iz = bc;
    e0.x *= iz; e0.y *= iz; e0.z *= iz; e0.w *= iz;
    e1.x *= iz; e1.y *= iz; e1.z *= iz; e1.w *= iz;
    sc[t] = e0;
    sc[t + 256] = e1;
}

// -------- fused k_rmm: 4 rows/block, SINGLE sweep, no rf array --------------
// scores gathered (normalized); S via idx2; e=exp(-wq*dist); Z,max,corr
// accumulated in registers; normalization deferred to the final reduction.
__global__ __launch_bounds__(256) void k_rmm(const int* __restrict__ idx1,
                                             const int* __restrict__ idx2,
                                             const float* __restrict__ tgt) {
    __shared__ float Trow[4][2048];
    __shared__ float redA[20][8];
    __shared__ float bc[4];
    int blk = blockIdx.x;
    int b = blk >> 9;
    int n0 = (blk & 511) * 4;
    int t = threadIdx.x, lane = t & 31, wid = t >> 5;

    // pass 1: build 4 T rows (gather+sum 7 normalized score rows each)
    const float4* base = (const float4*)(g_sc + (size_t)(b << 11) * Mv);
#pragma unroll
    for (int r = 0; r < 4; r++) {
        const int* ip = idx1 + (size_t)((b << 11) + n0 + r) * K1v;
        const float4* r0 = base + (size_t)ip[1] * 512;
        const float4* r1 = base + (size_t)ip[2] * 512;
        const float4* r2 = base + (size_t)ip[3] * 512;
        const float4* r3 = base + (size_t)ip[4] * 512;
        const float4* r4 = base + (size_t)ip[5] * 512;
        const float4* r5 = base + (size_t)ip[6] * 512;
        const float4* r6 = base + (size_t)ip[7] * 512;
        float4* Tv = (float4*)Trow[r];
        for (int q = t; q < 512; q += 256) {
            float4 a0 = r0[q], a1 = r1[q], a2 = r2[q], a3 = r3[q];
            float4 a4 = r4[q], a5 = r5[q], a6 = r6[q];
            float4 o;
            o.x = ((a0.x + a1.x) + (a2.x + a3.x)) + ((a4.x + a5.x) + a6.x);
            o.y = ((a0.y + a1.y) + (a2.y + a3.y)) + ((a4.y + a5.y) + a6.y);
            o.z = ((a0.z + a1.z) + (a2.z + a3.z)) + ((a4.z + a5.z) + a6.z);
            o.w = ((a0.w + a1.w) + (a2.w + a3.w)) + ((a4.w + a5.w) + a6.w);
            Tv[q] = o;
        }
    }
    __syncthreads();

    // pass 2: single sweep — S gather, refined exp, Z/max/corr accumulation
    const float* dp0 = g_dist + (size_t)((b << 11) + n0) * Mv;
    const int4* i2 = (const int4*)(idx2 + (size_t)b * Mv * K1v);
    const float* t0 = tgt + (size_t)b * 3 * Mv;
    float zs[4] = {0.f, 0.f, 0.f, 0.f};
    float em[4] = {0.f, 0.f, 0.f, 0.f};
    float acc[12];
#pragma unroll
    for (int i = 0; i < 12; i++) acc[i] = 0.f;
    for (int m = t; m < Mv; m += 256) {
        int4 lo = i2[m * 2], hi = i2[m * 2 + 1];
        float v0 = t0[m], v1 = t0[Mv + m], v2 = t0[2 * Mv + m];
#pragma unroll
        for (int r = 0; r < 4; r++) {
            const float* T = Trow[r];
            float S = T[lo.y] + T[lo.z] + T[lo.w] +
                      T[hi.x] + T[hi.y] + T[hi.z] + T[hi.w];
            float wq = __expf(1.0f - S * (1.0f / 7.0f));
            float e = __expf(-wq * dp0[(size_t)r * Mv + m]);
            zs[r] += e;
            em[r] = fmaxf(em[r], e);
            acc[r * 3 + 0] = fmaf(v0, e, acc[r * 3 + 0]);
            acc[r * 3 + 1] = fmaf(v1, e, acc[r * 3 + 1]);
            acc[r * 3 + 2] = fmaf(v2, e, acc[r * 3 + 2]);
        }
    }

    // batched reduction: rows 0-3 = Z, 4-7 = max, 8-19 = corr sums
#pragma unroll
    for (int r = 0; r < 4; r++) {
        float z = zs[r], mx = em[r];
#pragma unroll
        for (int o = 16; o; o >>= 1) {
            z += __shfl_xor_sync(~0u, z, o);
            mx = fmaxf(mx, __shfl_xor_sync(~0u, mx, o));
        }
        if (lane == 0) { redA[r][wid] = z; redA[4 + r][wid] = mx; }
    }
#pragma unroll
    for (int i = 0; i < 12; i++) {
        float v = acc[i];
#pragma unroll
        for (int o = 16; o; o >>= 1) v += __shfl_xor_sync(~0u, v, o);
        if (lane == 0) redA[8 + i][wid] = v;
    }
    __syncthreads();
    if (t < 4) {
        float z = 0.f;
#pragma unroll
        for (int j = 0; j < 8; j++) z += redA[t][j];
        bc[t] = 1.0f / z;
    }
    __syncthreads();
    if (t >= 4 && t < 8) {
        int r = t - 4;
        float mx = 0.f;
#pragma unroll
        for (int j = 0; j < 8; j++) mx = fmaxf(mx, redA[t][j]);
        g_maxp[(b << 11) + n0 + r] = mx * bc[r];
    } else if (t >= 8 && t < 20) {
        int i = t - 8;
        float s = 0.f;
#pragma unroll
        for (int j = 0; j < 8; j++) s += redA[t][j];
        int r = i / 3, cc = i % 3;
        g_scorr[(b * 3 + cc) * Nv + n0 + r] = s * bc[r];
    }
}

// ---------------- discriminator MLP + max over k ----------------------------
__global__ __launch_bounds__(256) void k_disc(const float* __restrict__ src,
                                              const float* __restrict__ src_knn,
                                              const int* __restrict__ src_idx,
                                              const float* __restrict__ W1, const float* __restrict__ b1,
                                              const float* __restrict__ W2, const float* __restrict__ b2,
                                              const float* __restrict__ W3, const float* __restrict__ b3) {
    __shared__ float sW1[H1v * 6], sb1[H1v], sW2[H2v * H1v], sb2[H2v], sW3[H2v];
    __shared__ float sb3s;
    int t = threadIdx.x;
    for (int i = t; i < H1v * 6; i += 256) sW1[i] = W1[i];
    for (int i = t; i < H1v; i += 256) sb1[i] = b1[i];
    for (int i = t; i < H2v * H1v; i += 256) sW2[i] = W2[i];
    for (int i = t; i < H2v; i += 256) { sb2[i] = b2[i]; sW3[i] = W3[i]; }
    if (t == 0) sb3s = b3[0];
    __syncthreads();

    int gid = blockIdx.x * 256 + t;
    int k = gid & (Kv - 1);
    int n = (gid >> 4) & (Nv - 1);
    int b = gid >> 15;
    int j = src_idx[(size_t)gid];
    float f[6];
#pragma unroll
    for (int c = 0; c < 3; c++) {
        f[c]     = g_scorr[(b * 3 + c) * Nv + n] - g_scorr[(b * 3 + c) * Nv + j];
        f[3 + c] = src[(size_t)(b * 3 + c) * Nv + n] - src_knn[(size_t)gid * 3 + c];
    }
    float h1[H1v];
#pragma unroll
    for (int d = 0; d < H1v; d++) {
        float a = sb1[d];
#pragma unroll
        for (int c = 0; c < 6; c++) a = fmaf(sW1[d * 6 + c], f[c], a);
        h1[d] = fmaxf(a, 0.f);
    }
    float s = sb3s;
    const float4* W2v = (const float4*)sW2;
    for (int e = 0; e < H2v; e++) {
        float a = sb2[e];
#pragma unroll
        for (int dq = 0; dq < 16; dq++) {
            float4 w = W2v[e * 16 + dq];
            a = fmaf(w.x, h1[dq * 4 + 0], a);
            a = fmaf(w.y, h1[dq * 4 + 1], a);
            a = fmaf(w.z, h1[dq * 4 + 2], a);
            a = fmaf(w.w, h1[dq * 4 + 3], a);
        }
        s = fmaf(sW3[e], fmaxf(a, 0.f), s);
    }
#pragma unroll
    for (int off = 8; off > 0; off >>= 1)
        s = fmaxf(s, __shfl_xor_sync(0xffffffffu, s, off, 16));
    if (k == 0) g_s[(b << 11) + n] = s;
}

// ------- fused: weight softmax + rigid sums + exact top-k (per batch) -------
__global__ __launch_bounds__(1024) void k_post(const float* __restrict__ src) {
    int b = blockIdx.x; int t = threadIdx.x;
    int lane = t & 31, wid = t >> 5;
    __shared__ float sv[2048];
    __shared__ int   si[2048];
    __shared__ float red32[32];
    __shared__ float bcast;
    const float* s = g_s + b * Nv;
    float v0 = s[t], v1 = s[t + 1024];
    float mx = fmaxf(v0, v1);
#pragma unroll
    for (int o = 16; o; o >>= 1) mx = fmaxf(mx, __shfl_xor_sync(~0u, mx, o));
    if (lane == 0) red32[wid] = mx;
    __syncthreads();
    if (wid == 0) {
        float m = red32[lane];
#pragma unroll
        for (int o = 16; o; o >>= 1) m = fmaxf(m, __shfl_xor_sync(~0u, m, o));
        if (lane == 0) bcast = m;
    }
    __syncthreads();
    mx = bcast;
    float e0 = __expf(v0 - mx), e1 = __expf(v1 - mx);
    float zs = e0 + e1;
#pragma unroll
    for (int o = 16; o; o >>= 1) zs += __shfl_xor_sync(~0u, zs, o);
    if (lane == 0) red32[wid] = zs;
    __syncthreads();
    if (wid == 0) {
        float z = red32[lane];
#pragma unroll
        for (int o = 16; o; o >>= 1) z += __shfl_xor_sync(~0u, z, o);
        if (lane == 0) bcast = z;
    }
    __syncthreads();
    float inv = 1.0f / bcast;
    float w0 = e0 * inv, w1 = e1 * inv;
    sv[t] = w0;          si[t] = t;
    sv[t + 1024] = w1;   si[t + 1024] = t + 1024;

    const float* sx = src + (size_t)b * 3 * Nv;
    const float* cx = g_scorr + (size_t)b * 3 * Nv;
    float a[15];
    {
        int n1 = t, n2 = t + 1024;
        float s10 = sx[n1], s11 = sx[Nv + n1], s12 = sx[2 * Nv + n1];
        float c10 = cx[n1], c11 = cx[Nv + n1], c12 = cx[2 * Nv + n1];
        float s20 = sx[n2], s21 = sx[Nv + n2], s22 = sx[2 * Nv + n2];
        float c20 = cx[n2], c21 = cx[Nv + n2], c22 = cx[2 * Nv + n2];
        a[0] = w0 * s10 + w1 * s20;
        a[1] = w0 * s11 + w1 * s21;
        a[2] = w0 * s12 + w1 * s22;
        a[3] = w0 * c10 + w1 * c20;
        a[4] = w0 * c11 + w1 * c21;
        a[5] = w0 * c12 + w1 * c22;
        a[6]  = w0 * s10 * c10 + w1 * s20 * c20;
        a[7]  = w0 * s10 * c11 + w1 * s20 * c21;
        a[8]  = w0 * s10 * c12 + w1 * s20 * c22;
        a[9]  = w0 * s11 * c10 + w1 * s21 * c20;
        a[10] = w0 * s11 * c11 + w1 * s21 * c21;
        a[11] = w0 * s11 * c12 + w1 * s21 * c22;
        a[12] = w0 * s12 * c10 + w1 * s22 * c20;
        a[13] = w0 * s12 * c11 + w1 * s22 * c21;
        a[14] = w0 * s12 * c12 + w1 * s22 * c22;
    }
#pragma unroll
    for (int r = 0; r < 15; r++) {
        float val = a[r];
#pragma unroll
        for (int o = 16; o; o >>= 1) val += __shfl_xor_sync(~0u, val, o);
        if (lane == 0) red32[wid] = val;
        __syncthreads();
        if (wid == 0) {
            float v = red32[lane];
#pragma unroll
            for (int o = 16; o; o >>= 1) v += __shfl_xor_sync(~0u, v, o);
            if (lane == 0) g_res[b * 15 + r] = v;
        }
        __syncthreads();
    }

    for (int kk = 2; kk <= 2048; kk <<= 1) {
        for (int j = kk >> 1; j > 0; j >>= 1) {
            int i = t;
            int ixj = i ^ j;
            if (ixj > i) {
                float av = sv[i], bvv = sv[ixj];
                int ai = si[i], bi = si[ixj];
                bool aFirst = (av > bvv) || (av == bvv && ai < bi);
                bool desc = ((i & kk) == 0);
                if (desc != aFirst) {
                    sv[i] = bvv; si[i] = bi;
                    sv[ixj] = av; si[ixj] = ai;
                }
            }
            i = t + 1024;
            ixj = i ^ j;
            if (ixj > i) {
                float av = sv[i], bvv = sv[ixj];
                int ai = si[i], bi = si[ixj];
                bool aFirst = (av > bvv) || (av == bvv && ai < bi);
                bool desc = ((i & kk) == 0);
                if (desc != aFirst) {
                    sv[i] = bvv; si[i] = bi;
                    sv[ixj] = av; si[ixj] = ai;
                }
            }
            __syncthreads();
        }
    }
    g_topi[b * KEYv + t] = si[t];
}

// ---------------- 3x3 helpers ------------------------------------------------
__device__ double det3(const double M[3][3]) {
    return M[0][0] * (M[1][1] * M[2][2] - M[1][2] * M[2][1])
         - M[0][1] * (M[1][0] * M[2][2] - M[1][2] * M[2][0])
         + M[0][2] * (M[1][0] * M[2][1] - M[1][1] * M[2][0]);
}

__device__ void kabsch_R(const double H[3][3], double R[3][3]) {
    double A[3][3], V[3][3];
    for (int i = 0; i < 3; i++)
        for (int j = 0; j < 3; j++) {
            A[i][j] = H[0][i] * H[0][j] + H[1][i] * H[1][j] + H[2][i] * H[2][j];
            V[i][j] = (i == j) ? 1.0 : 0.0;
        }
    for (int sweep = 0; sweep < 12; sweep++) {
        double off = fabs(A[0][1]) + fabs(A[0][2]) + fabs(A[1][2]);
        if (off == 0.0) break;
        const int PQ[3][2] = {{0, 1}, {0, 2}, {1, 2}};
        for (int pi = 0; pi < 3; pi++) {
            int p = PQ[pi][0], q = PQ[pi][1];
            double apq = A[p][q];
            if (fabs(apq) < 1e-300) continue;
            double app = A[p][p], aqq = A[q][q];
            double tau = (aqq - app) / (2.0 * apq);
            double tt = (tau >= 0.0 ? 1.0 : -1.0) / (fabs(tau) + sqrt(1.0 + tau * tau));
            double cc = 1.0 / sqrt(1.0 + tt * tt);
            double ss = tt * cc;
            A[p][p] = app - tt * apq; A[q][q] = aqq + tt * apq;
            A[p][q] = 0.0; A[q][p] = 0.0;
            int r = 3 - p - q;
            double arp = A[r][p], arq = A[r][q];
            A[r][p] = cc * arp - ss * arq; A[p][r] = A[r][p];
            A[r][q] = ss * arp + cc * arq; A[q][r] = A[r][q];
            for (int i = 0; i < 3; i++) {
                double vp = V[i][p], vq = V[i][q];
                V[i][p] = cc * vp - ss * vq;
                V[i][q] = ss * vp + cc * vq;
            }
        }
    }
    double lam[3] = {A[0][0], A[1][1], A[2][2]};
    int ord[3] = {0, 1, 2};
    if (lam[ord[0]] < lam[ord[1]]) { int tmp = ord[0]; ord[0] = ord[1]; ord[1] = tmp; }
    if (lam[ord[0]] < lam[ord[2]]) { int tmp = ord[0]; ord[0] = ord[2]; ord[2] = tmp; }
    if (lam[ord[1]] < lam[ord[2]]) { int tmp = ord[1]; ord[1] = ord[2]; ord[2] = tmp; }
    double Vs[3][3], S[3], U[3][3];
    for (int k = 0; k < 3; k++) {
        int o = ord[k];
        S[k] = sqrt(fmax(lam[o], 0.0));
        for (int i = 0; i < 3; i++) Vs[i][k] = V[i][o];
    }
    for (int k = 0; k < 3; k++) {
        if (S[k] > 1e-12) {
            double inv = 1.0 / S[k];
            for (int i = 0; i < 3; i++)
                U[i][k] = (H[i][0] * Vs[0][k] + H[i][1] * Vs[1][k] + H[i][2] * Vs[2][k]) * inv;
        } else {
            U[0][k] = U[1][0] * U[2][1] - U[2][0] * U[1][1];
            U[1][k] = U[2][0] * U[0][1] - U[0][0] * U[2][1];
            U[2][k] = U[0][0] * U[1][1] - U[1][0] * U[0][1];
        }
    }
    double d = det3(U) * det3(Vs);
    for (int i = 0; i < 3; i++)
        for (int j = 0; j < 3; j++)
            R[i][j] = Vs[i][0] * U[j][0] + Vs[i][1] * U[j][1] + d * Vs[i][2] * U[j][2];
}

// ---------------- SVD / rigid transform (1 thread per batch) ----------------
__global__ void k_svd(float* __restrict__ out) {
    int b = blockIdx.x;
    if (threadIdx.x != 0) return;
    const float* res = g_res + b * 15;
    double cs[3] = {res[0], res[1], res[2]};
    double ct[3] = {res[3], res[4], res[5]};
    double H[3][3];
    for (int i = 0; i < 3; i++)
        for (int j = 0; j < 3; j++)
            H[i][j] = (double)res[6 + i * 3 + j] - cs[i] * ct[j];
    double R[3][3];
    kabsch_R(H, R);
    double tv[3];
    for (int i = 0; i < 3; i++)
        tv[i] = ct[i] - (R[i][0] * cs[0] + R[i][1] * cs[1] + R[i][2] * cs[2]);
    for (int i = 0; i < 3; i++)
        for (int j = 0; j < 3; j++) {
            out[OFF_R + b * 9 + i * 3 + j] = (float)R[i][j];
            g_R[b * 9 + i * 3 + j] = (float)R[i][j];
        }
    for (int i = 0; i < 3; i++) {
        out[OFF_T + b * 3 + i] = (float)tv[i];
        g_tv[b * 3 + i] = (float)tv[i];
    }
}

// ---------------- keypoint outputs (transform inline) -----------------------
__global__ void k_out(const float* __restrict__ src, const int* __restrict__ src_idx,
                      float* __restrict__ out) {
    int gid = blockIdx.x * 256 + threadIdx.x;
    int k = gid & (Kv - 1);
    int jj = (gid >> 4) & (KEYv - 1);
    int b = gid >> 14;
    const float* R = g_R + b * 9;
    float R00 = R[0], R01 = R[1], R02 = R[2];
    float R10 = R[3], R11 = R[4], R12 = R[5];
    float R20 = R[6], R21 = R[7], R22 = R[8];
    int n = g_topi[b * KEYv + jj];
    int m = src_idx[((size_t)(b * Nv) + n) * Kv + k];
    const float* sb = src + (size_t)b * 3 * Nv;
    const float* cb = g_scorr + (size_t)b * 3 * Nv;
    float sn0 = sb[n], sn1 = sb[Nv + n], sn2 = sb[2 * Nv + n];
    float sm0 = sb[m], sm1 = sb[Nv + m], sm2 = sb[2 * Nv + m];
    float d0 = sn0 - sm0, d1 = sn1 - sm1, d2 = sn2 - sm2;
    float sk0 = R00 * d0 + R01 * d1 + R02 * d2;
    float sk1 = R10 * d0 + R11 * d1 + R12 * d2;
    float sk2 = R20 * d0 + R21 * d1 + R22 * d2;
    size_t o0 = ((size_t)(b * 3 + 0) * KEYv + jj) * Kv + k;
    size_t o1 = ((size_t)(b * 3 + 1) * KEYv + jj) * Kv + k;
    size_t o2 = ((size_t)(b * 3 + 2) * KEYv + jj) * Kv + k;
    out[OFF_SKK + o0] = sk0;
    out[OFF_SKK + o1] = sk1;
    out[OFF_SKK + o2] = sk2;
    float cn0 = cb[n], cn1 = cb[Nv + n], cn2 = cb[2 * Nv + n];
    out[OFF_TKK + o0] = cn0 - cb[m];
    out[OFF_TKK + o1] = cn1 - cb[Nv + m];
    out[OFF_TKK + o2] = cn2 - cb[2 * Nv + m];
    if (k == 0) {
        out[OFF_SK + (size_t)(b * 3 + 0) * KEYv + jj] = sn0;
        out[OFF_SK + (size_t)(b * 3 + 1) * KEYv + jj] = sn1;
        out[OFF_SK + (size_t)(b * 3 + 2) * KEYv + jj] = sn2;
        out[OFF_TK + (size_t)(b * 3 + 0) * KEYv + jj] = cn0;
        out[OFF_TK + (size_t)(b * 3 + 1) * KEYv + jj] = cn1;
        out[OFF_TK + (size_t)(b * 3 + 2) * KEYv + jj] = cn2;
    }
}

// ---------------- loss -------------------------------------------------------
__global__ __launch_bounds__(1024) void k_loss(float* __restrict__ out) {
    __shared__ float red[1024];
    int t = threadIdx.x;
    float acc = 0.f;
    for (int idx = t; idx < Bv * KEYv; idx += 1024) {
        int b = idx >> 10;
        int n = g_topi[idx];
        acc += -__logf(g_maxp[b * Nv + n] + 1e-15f);
    }
    red[t] = acc; __syncthreads();
    for (int st = 512; st > 0; st >>= 1) { if (t < st) red[t] += red[t + st]; __syncthreads(); }
    if (t == 0) out[OFF_LOSS] = red[0] * (1.0f / (Bv * KEYv));
}

// ---------------- launch -----------------------------------------------------
extern "C" void kernel_launch(void* const* d_in, const int* in_sizes, int n_in,
                              void* d_out, int out_size) {
    const float* src   = (const float*)d_in[0];
    const float* tgt   = (const float*)d_in[1];
    const float* semb  = (const float*)d_in[2];
    const float* temb  = (const float*)d_in[3];
    const float* sknn  = (const float*)d_in[4];
    const float* W1    = (const float*)d_in[6];
    const float* b1    = (const float*)d_in[7];
    const float* W2    = (const float*)d_in[8];
    const float* b2    = (const float*)d_in[9];
    const float* W3    = (const float*)d_in[10];
    const float* b3    = (const float*)d_in[11];
    const int*   sidx  = (const int*)d_in[12];
    const int*   sidx1 = (const int*)d_in[13];
    const int*   idx2  = (const int*)d_in[14];
    float* out = (float*)d_out;

    cudaFuncSetAttribute(k_mm, cudaFuncAttributeMaxDynamicSharedMemorySize, MM_SMEM);

    __nv_bfloat16* A2;
    __nv_bfloat16* B2;
    cudaGetSymbolAddress((void**)&A2, g_A2);
    cudaGetSymbolAddress((void**)&B2, g_B2);
    float* distp;
    cudaGetSymbolAddress((void**)&distp, g_dist);
    float* xxp;
    float* yyp;
    cudaGetSymbolAddress((void**)&xxp, g_xx);
    cudaGetSymbolAddress((void**)&yyp, g_yy);

    k_zero<<<16, 256>>>();
    dim3 cg(64, 16, 2);
    k_conv<<<cg, 256>>>(semb, A2, xxp);
    k_conv<<<cg, 256>>>(temb, B2, yyp);
    dim3 gg(Mv / 128, Nv / 128, Bv);
    k_mm<<<gg, 256, MM_SMEM>>>(distp);
    k_scores<<<Bv * Nv, 256>>>();
    k_rmm<<<Bv * Nv / 4, 256>>>(sidx1, idx2, tgt);
    k_disc<<<(Bv * Nv * Kv) / 256, 256>>>(src, sknn, sidx, W1, b1, W2, b2, W3, b3);
    k_post<<<Bv, 1024>>>(src);
    k_svd<<<Bv, 1>>>(out);
    k_out<<<(Bv * KEYv * Kv) / 256, 256>>>(src, sidx, out);
    k_loss<<<1, 1024>>>(out);
}

// round 11
// speedup vs baseline: 2.0271x; 1.1381x over previous
#include <cuda_runtime.h>
#include <cuda_bf16.h>
#include <math.h>
#include <stdint.h>

#define Bv   2
#define Nv   2048
#define Mv   2048
#define Cv   512
#define Kv   16
#define K1v  8
#define KEYv 1024
#define H1v  64
#define H2v  128

// d_out layout: R[2,3,3] | tvec[2,3] | src_kp[2,3,1024] | tgt_kp[2,3,1024]
//             | src_kp_knn[2,3,1024,16] | tgt_kp_knn[2,3,1024,16] | loss
#define OFF_R    0
#define OFF_T    18
#define OFF_SK   24
#define OFF_TK   (24 + 6144)
#define OFF_SKK  (24 + 12288)
#define OFF_TKK  (24 + 12288 + 98304)
#define OFF_LOSS (24 + 12288 + 196608)

// ---------------- scratch (device globals; no allocation allowed) -----------
__device__ float g_dist[Bv * Nv * Mv];   // 33.5 MB
__device__ float g_sc  [Bv * Nv * Mv];   // 33.5 MB  scores = softmax(-dist)
__device__ float g_xx[Bv * Nv];
__device__ float g_yy[Bv * Mv];
__device__ float g_z [Bv * Nv];
__device__ float g_scorr[Bv * 3 * Nv];
__device__ float g_maxp[Bv * Nv];
__device__ float g_s[Bv * Nv];
__device__ int   g_topi[Bv * KEYv];
__device__ float g_R[Bv * 9];
__device__ float g_tv[Bv * 3];
__device__ float g_res[Bv * 15];
// bf16 split embeddings, [b][n][0..511]=hi, [b][n][512..1023]=lo  (k-contig)
__device__ __align__(256) __nv_bfloat16 g_A2[Bv * Nv * 1024];
__device__ __align__(256) __nv_bfloat16 g_B2[Bv * Mv * 1024];

// =================== helpers ================================================
__device__ __forceinline__ uint32_t smem_to_u32(const void* p) {
    uint32_t a;
    asm("{ .reg .u64 t; cvta.to.shared.u64 t, %1; cvt.u32.u64 %0, t; }" : "=r"(a) : "l"(p));
    return a;
}
static __device__ __forceinline__ void cp_async16(uint32_t dst, const void* src) {
    asm volatile("cp.async.cg.shared.global [%0], [%1], 16;" :: "r"(dst), "l"(src) : "memory");
}
static __device__ __forceinline__ void ldm_x4(uint32_t* r, uint32_t addr) {
    asm volatile("ldmatrix.sync.aligned.m8n8.x4.shared.b16 {%0,%1,%2,%3}, [%4];"
                 : "=r"(r[0]), "=r"(r[1]), "=r"(r[2]), "=r"(r[3]) : "r"(addr));
}
static __device__ __forceinline__ void mma16816(float* c, const uint32_t* a,
                                                uint32_t b0, uint32_t b1) {
    asm volatile(
        "mma.sync.aligned.m16n8k16.row.col.f32.bf16.bf16.f32 "
        "{%0,%1,%2,%3},{%4,%5,%6,%7},{%8,%9},{%0,%1,%2,%3};"
        : "+f"(c[0]), "+f"(c[1]), "+f"(c[2]), "+f"(c[3])
        : "r"(a[0]), "r"(a[1]), "r"(a[2]), "r"(a[3]), "r"(b0), "r"(b1));
}

// ---------------- zero accumulators (FROZEN: round-7 upstream) --------------
__global__ void k_zero() {
    int i = blockIdx.x * 256 + threadIdx.x;
    g_xx[i] = 0.f;
    g_yy[i] = 0.f;
    g_z[i]  = 0.f;
}

// ------- fp32 -> bf16 hi/lo transpose-split + fused column sq-norms ---------
// FROZEN: round-7 upstream (summation order affects topi tie resolution).
__global__ __launch_bounds__(256) void k_conv(const float* __restrict__ e,
                                              __nv_bfloat16* __restrict__ out,
                                              float* __restrict__ norm) {
    __shared__ float ts[32][33];
    __shared__ float colsum[32];
    int b = blockIdx.z, c0 = blockIdx.y * 32, n0 = blockIdx.x * 32;
    int tx = threadIdx.x & 31, ty = threadIdx.x >> 5;
    if (threadIdx.x < 32) colsum[threadIdx.x] = 0.f;
    __syncthreads();
    float ps = 0.f;
    for (int i = ty; i < 32; i += 8) {
        float v = e[((size_t)b * Cv + c0 + i) * 2048 + n0 + tx];
        ts[i][tx] = v;
        ps = fmaf(v, v, ps);
    }
    atomicAdd(&colsum[tx], ps);
    __syncthreads();
    if (threadIdx.x < 32)
        atomicAdd(&norm[b * 2048 + n0 + threadIdx.x], colsum[threadIdx.x]);
    for (int i = ty; i < 32; i += 8) {
        float x = ts[tx][i];
        __nv_bfloat16 h = __float2bfloat16(x);
        __nv_bfloat16 l = __float2bfloat16(x - __bfloat162float(h));
        size_t base = ((size_t)b * 2048 + n0 + i) * 1024 + c0 + tx;
        out[base] = h;
        out[base + 512] = l;
    }
}

// ---------------- bf16 mma.sync GEMM: dist = xx - 2*A.B^T + yy --------------
// FROZEN: round-7 upstream. CTA tile 128x128; K'=1536 as 24 chunks of 64.
#define MM_SMEM (6 * 16384)

__global__ __launch_bounds__(256) void k_mm(float* __restrict__ dist) {
    extern __shared__ char smem[];
    const uint32_t sbA = smem_to_u32(smem);            // 3 bufs x 128 rows x 128B
    const uint32_t sbB = sbA + 49152;                  // 3 bufs x 128 rows x 128B
    const int tid = threadIdx.x;
    const int lane = tid & 31, wid = tid >> 5;
    const int warp_m = (wid >> 1) * 32;
    const int warp_n = (wid & 1) * 64;
    const int bz = blockIdx.z;
    const int row0 = blockIdx.y * 128;
    const int col0 = blockIdx.x * 128;

    const char* Arow = (const char*)(g_A2 + ((size_t)bz * 2048 + row0) * 1024);
    const char* Brow = (const char*)(g_B2 + ((size_t)bz * 2048 + col0) * 1024);

    float c[2][8][4];
#pragma unroll
    for (int mt = 0; mt < 2; mt++)
#pragma unroll
        for (int nt = 0; nt < 8; nt++)
#pragma unroll
            for (int q = 0; q < 4; q++) c[mt][nt][q] = 0.f;

    auto load_chunk = [&](int it, int stage) {
        const int ab = ((it >= 16) ? 512 : 0) + (it & 7) * 64;
        const int bb = ((it >= 8 && it < 16) ? 512 : 0) + (it & 7) * 64;
        const char* ap = Arow + ab * 2;
        const char* bp = Brow + bb * 2;
        const uint32_t ad = sbA + stage * 16384;
        const uint32_t bd = sbB + stage * 16384;
#pragma unroll
        for (int u = 0; u < 4; u++) {
            int o = tid + u * 256;
            int r = o >> 3, s = o & 7;
            uint32_t sw = ((uint32_t)(s ^ (r & 7))) << 4;
            cp_async16(ad + r * 128 + sw, ap + (size_t)r * 2048 + s * 16);
            cp_async16(bd + r * 128 + sw, bp + (size_t)r * 2048 + s * 16);
        }
        asm volatile("cp.async.commit_group;" ::: "memory");
    };

    load_chunk(0, 0);
    load_chunk(1, 1);

    for (int it = 0; it < 24; it++) {
        if (it < 23) asm volatile("cp.async.wait_group 1;" ::: "memory");
        else         asm volatile("cp.async.wait_group 0;" ::: "memory");
        __syncthreads();
        if (it + 2 < 24) load_chunk(it + 2, (it + 2) % 3);

        const int buf = it % 3;
        const uint32_t aB = sbA + buf * 16384;
        const uint32_t bB = sbB + buf * 16384;
#pragma unroll
        for (int kk = 0; kk < 4; kk++) {
            uint32_t afr[2][4];
#pragma unroll
            for (int mt = 0; mt < 2; mt++) {
                int row = warp_m + mt * 16 + (lane & 7) + ((lane >> 3) & 1) * 8;
                int ch = 2 * kk + (lane >> 4);
                ldm_x4(afr[mt], aB + row * 128 + (((uint32_t)(ch ^ (row & 7))) << 4));
            }
            uint32_t bfr[4][4];
#pragma unroll
            for (int nt = 0; nt < 4; nt++) {
                int sel = lane >> 3;
                int row = warp_n + nt * 16 + (lane & 7) + (sel >> 1) * 8;
                int ch = 2 * kk + (sel & 1);
                ldm_x4(bfr[nt], bB + row * 128 + (((uint32_t)(ch ^ (row & 7))) << 4));
            }
#pragma unroll
            for (int mt = 0; mt < 2; mt++)
#pragma unroll
                for (int n8 = 0; n8 < 8; n8++)
                    mma16816(c[mt][n8], afr[mt],
                             bfr[n8 >> 1][(n8 & 1) * 2], bfr[n8 >> 1][(n8 & 1) * 2 + 1]);
        }
    }

    const int grp = lane >> 2, qp = lane & 3;
#pragma unroll
    for (int mt = 0; mt < 2; mt++) {
        int m = warp_m + mt * 16 + grp;
        float x0 = g_xx[bz * 2048 + row0 + m];
        float x1 = g_xx[bz * 2048 + row0 + m + 8];
        float* d0 = dist + ((size_t)(bz * 2048 + row0 + m)) * 2048 + col0;
        float* d1 = d0 + (size_t)8 * 2048;
#pragma unroll
        for (int n8 = 0; n8 < 8; n8++) {
            int n = warp_n + n8 * 8 + qp * 2;
            float y0 = g_yy[bz * 2048 + col0 + n];
            float y1 = g_yy[bz * 2048 + col0 + n + 1];
            float2 v0, v1;
            v0.x = fmaf(-2.f, c[mt][n8][0], x0 + y0);
            v0.y = fmaf(-2.f, c[mt][n8][1], x0 + y1);
            v1.x = fmaf(-2.f, c[mt][n8][2], x1 + y0);
            v1.y = fmaf(-2.f, c[mt][n8][3], x1 + y1);
            *(float2*)(d0 + n) = v0;
            *(float2*)(d1 + n) = v1;
        }
    }
}

// ---------------- scores = softmax(-dist) row-wise (FROZEN) -----------------
__global__ __launch_bounds__(256) void k_scores() {
    int row = blockIdx.x;
    const float4* d = (const float4*)(g_dist + (size_t)row * Mv);
    float4* sc = (float4*)(g_sc + (size_t)row * Mv);
    __shared__ float red[8];
    __shared__ float bc;
    int t = threadIdx.x, lane = t & 31, wid = t >> 5;
    float4 v0 = d[t], v1 = d[t + 256];
    float4 e0, e1;
    e0.x = __expf(-v0.x); e0.y = __expf(-v0.y); e0.z = __expf(-v0.z); e0.w = __expf(-v0.w);
    e1.x = __expf(-v1.x); e1.y = __expf(-v1.y); e1.z = __expf(-v1.z); e1.w = __expf(-v1.w);
    float zs = (e0.x + e0.y) + (e0.z + e0.w) + (e1.x + e1.y) + (e1.z + e1.w);
#pragma unroll
    for (int o = 16; o; o >>= 1) zs += __shfl_xor_sync(~0u, zs, o);
    if (lane == 0) red[wid] = zs;
    __syncthreads();
    if (t == 0) {
        float z = 0.f;
#pragma unroll
        for (int i = 0; i < 8; i++) z += red[i];
        bc = 1.0f / z;
    }
    __syncthreads();
    float iz = bc;
    e0.x *= iz; e0.y *= iz; e0.z *= iz; e0.w *= iz;
    e1.x *= iz; e1.y *= iz; e1.z *= iz; e1.w *= iz;
    sc[t] = e0;
    sc[t + 256] = e1;
}

// -------- fused k_rmm: 4 rows/block, single sweep (FROZEN) ------------------
__global__ __launch_bounds__(256) void k_rmm(const int* __restrict__ idx1,
                                             const int* __restrict__ idx2,
                                             const float* __restrict__ tgt) {
    __shared__ float Trow[4][2048];
    __shared__ float redA[20][8];
    __shared__ float bc[4];
    int blk = blockIdx.x;
    int b = blk >> 9;
    int n0 = (blk & 511) * 4;
    int t = threadIdx.x, lane = t & 31, wid = t >> 5;

    const float4* base = (const float4*)(g_sc + (size_t)(b << 11) * Mv);
#pragma unroll
    for (int r = 0; r < 4; r++) {
        const int* ip = idx1 + (size_t)((b << 11) + n0 + r) * K1v;
        const float4* r0 = base + (size_t)ip[1] * 512;
        const float4* r1 = base + (size_t)ip[2] * 512;
        const float4* r2 = base + (size_t)ip[3] * 512;
        const float4* r3 = base + (size_t)ip[4] * 512;
        const float4* r4 = base + (size_t)ip[5] * 512;
        const float4* r5 = base + (size_t)ip[6] * 512;
        const float4* r6 = base + (size_t)ip[7] * 512;
        float4* Tv = (float4*)Trow[r];
        for (int q = t; q < 512; q += 256) {
            float4 a0 = r0[q], a1 = r1[q], a2 = r2[q], a3 = r3[q];
            float4 a4 = r4[q], a5 = r5[q], a6 = r6[q];
            float4 o;
            o.x = ((a0.x + a1.x) + (a2.x + a3.x)) + ((a4.x + a5.x) + a6.x);
            o.y = ((a0.y + a1.y) + (a2.y + a3.y)) + ((a4.y + a5.y) + a6.y);
            o.z = ((a0.z + a1.z) + (a2.z + a3.z)) + ((a4.z + a5.z) + a6.z);
            o.w = ((a0.w + a1.w) + (a2.w + a3.w)) + ((a4.w + a5.w) + a6.w);
            Tv[q] = o;
        }
    }
    __syncthreads();

    const float* dp0 = g_dist + (size_t)((b << 11) + n0) * Mv;
    const int4* i2 = (const int4*)(idx2 + (size_t)b * Mv * K1v);
    const float* t0 = tgt + (size_t)b * 3 * Mv;
    float zs[4] = {0.f, 0.f, 0.f, 0.f};
    float em[4] = {0.f, 0.f, 0.f, 0.f};
    float acc[12];
#pragma unroll
    for (int i = 0; i < 12; i++) acc[i] = 0.f;
    for (int m = t; m < Mv; m += 256) {
        int4 lo = i2[m * 2], hi = i2[m * 2 + 1];
        float v0 = t0[m], v1 = t0[Mv + m], v2 = t0[2 * Mv + m];
#pragma unroll
        for (int r = 0; r < 4; r++) {
            const float* T = Trow[r];
            float S = T[lo.y] + T[lo.z] + T[lo.w] +
                      T[hi.x] + T[hi.y] + T[hi.z] + T[hi.w];
            float wq = __expf(1.0f - S * (1.0f / 7.0f));
            float e = __expf(-wq * dp0[(size_t)r * Mv + m]);
            zs[r] += e;
            em[r] = fmaxf(em[r], e);
            acc[r * 3 + 0] = fmaf(v0, e, acc[r * 3 + 0]);
            acc[r * 3 + 1] = fmaf(v1, e, acc[r * 3 + 1]);
            acc[r * 3 + 2] = fmaf(v2, e, acc[r * 3 + 2]);
        }
    }

#pragma unroll
    for (int r = 0; r < 4; r++) {
        float z = zs[r], mx = em[r];
#pragma unroll
        for (int o = 16; o; o >>= 1) {
            z += __shfl_xor_sync(~0u, z, o);
            mx = fmaxf(mx, __shfl_xor_sync(~0u, mx, o));
        }
        if (lane == 0) { redA[r][wid] = z; redA[4 + r][wid] = mx; }
    }
#pragma unroll
    for (int i = 0; i < 12; i++) {
        float v = acc[i];
#pragma unroll
        for (int o = 16; o; o >>= 1) v += __shfl_xor_sync(~0u, v, o);
        if (lane == 0) redA[8 + i][wid] = v;
    }
    __syncthreads();
    if (t < 4) {
        float z = 0.f;
#pragma unroll
        for (int j = 0; j < 8; j++) z += redA[t][j];
        bc[t] = 1.0f / z;
    }
    __syncthreads();
    if (t >= 4 && t < 8) {
        int r = t - 4;
        float mx = 0.f;
#pragma unroll
        for (int j = 0; j < 8; j++) mx = fmaxf(mx, redA[t][j]);
        g_maxp[(b << 11) + n0 + r] = mx * bc[r];
    } else if (t >= 8 && t < 20) {
        int i = t - 8;
        float s = 0.f;
#pragma unroll
        for (int j = 0; j < 8; j++) s += redA[t][j];
        int r = i / 3, cc = i % 3;
        g_scorr[(b * 3 + cc) * Nv + n0 + r] = s * bc[r];
    }
}

// ---------------- discriminator MLP + max over k (FROZEN) -------------------
__global__ __launch_bounds__(256) void k_disc(const float* __restrict__ src,
                                              const float* __restrict__ src_knn,
                                              const int* __restrict__ src_idx,
                                              const float* __restrict__ W1, const float* __restrict__ b1,
                                              const float* __restrict__ W2, const float* __restrict__ b2,
                                              const float* __restrict__ W3, const float* __restrict__ b3) {
    __shared__ float sW1[H1v * 6], sb1[H1v], sW2[H2v * H1v], sb2[H2v], sW3[H2v];
    __shared__ float sb3s;
    int t = threadIdx.x;
    for (int i = t; i < H1v * 6; i += 256) sW1[i] = W1[i];
    for (int i = t; i < H1v; i += 256) sb1[i] = b1[i];
    for (int i = t; i < H2v * H1v; i += 256) sW2[i] = W2[i];
    for (int i = t; i < H2v; i += 256) { sb2[i] = b2[i]; sW3[i] = W3[i]; }
    if (t == 0) sb3s = b3[0];
    __syncthreads();

    int gid = blockIdx.x * 256 + t;
    int k = gid & (Kv - 1);
    int n = (gid >> 4) & (Nv - 1);
    int b = gid >> 15;
    int j = src_idx[(size_t)gid];
    float f[6];
#pragma unroll
    for (int c = 0; c < 3; c++) {
        f[c]     = g_scorr[(b * 3 + c) * Nv + n] - g_scorr[(b * 3 + c) * Nv + j];
        f[3 + c] = src[(size_t)(b * 3 + c) * Nv + n] - src_knn[(size_t)gid * 3 + c];
    }
    float h1[H1v];
#pragma unroll
    for (int d = 0; d < H1v; d++) {
        float a = sb1[d];
#pragma unroll
        for (int c = 0; c < 6; c++) a = fmaf(sW1[d * 6 + c], f[c], a);
        h1[d] = fmaxf(a, 0.f);
    }
    float s = sb3s;
    const float4* W2v = (const float4*)sW2;
    for (int e = 0; e < H2v; e++) {
        float a = sb2[e];
#pragma unroll
        for (int dq = 0; dq < 16; dq++) {
            float4 w = W2v[e * 16 + dq];
            a = fmaf(w.x, h1[dq * 4 + 0], a);
            a = fmaf(w.y, h1[dq * 4 + 1], a);
            a = fmaf(w.z, h1[dq * 4 + 2], a);
            a = fmaf(w.w, h1[dq * 4 + 3], a);
        }
        s = fmaf(sW3[e], fmaxf(a, 0.f), s);
    }
#pragma unroll
    for (int off = 8; off > 0; off >>= 1)
        s = fmaxf(s, __shfl_xor_sync(0xffffffffu, s, off, 16));
    if (k == 0) g_s[(b << 11) + n] = s;
}

// ------- fused: weight softmax + rigid sums + exact top-k (FROZEN) ----------
__global__ __launch_bounds__(1024) void k_post(const float* __restrict__ src) {
    int b = blockIdx.x; int t = threadIdx.x;
    int lane = t & 31, wid = t >> 5;
    __shared__ float sv[2048];
    __shared__ int   si[2048];
    __shared__ float red32[32];
    __shared__ float bcast;
    const float* s = g_s + b * Nv;
    float v0 = s[t], v1 = s[t + 1024];
    float mx = fmaxf(v0, v1);
#pragma unroll
    for (int o = 16; o; o >>= 1) mx = fmaxf(mx, __shfl_xor_sync(~0u, mx, o));
    if (lane == 0) red32[wid] = mx;
    __syncthreads();
    if (wid == 0) {
        float m = red32[lane];
#pragma unroll
        for (int o = 16; o; o >>= 1) m = fmaxf(m, __shfl_xor_sync(~0u, m, o));
        if (lane == 0) bcast = m;
    }
    __syncthreads();
    mx = bcast;
    float e0 = __expf(v0 - mx), e1 = __expf(v1 - mx);
    float zs = e0 + e1;
#pragma unroll
    for (int o = 16; o; o >>= 1) zs += __shfl_xor_sync(~0u, zs, o);
    if (lane == 0) red32[wid] = zs;
    __syncthreads();
    if (wid == 0) {
        float z = red32[lane];
#pragma unroll
        for (int o = 16; o; o >>= 1) z += __shfl_xor_sync(~0u, z, o);
        if (lane == 0) bcast = z;
    }
    __syncthreads();
    float inv = 1.0f / bcast;
    float w0 = e0 * inv, w1 = e1 * inv;
    sv[t] = w0;          si[t] = t;
    sv[t + 1024] = w1;   si[t + 1024] = t + 1024;

    const float* sx = src + (size_t)b * 3 * Nv;
    const float* cx = g_scorr + (size_t)b * 3 * Nv;
    float a[15];
    {
        int n1 = t, n2 = t + 1024;
        float s10 = sx[n1], s11 = sx[Nv + n1], s12 = sx[2 * Nv + n1];
        float c10 = cx[n1], c11 = cx[Nv + n1], c12 = cx[2 * Nv + n1];
        float s20 = sx[n2], s21 = sx[Nv + n2], s22 = sx[2 * Nv + n2];
        float c20 = cx[n2], c21 = cx[Nv + n2], c22 = cx[2 * Nv + n2];
        a[0] = w0 * s10 + w1 * s20;
        a[1] = w0 * s11 + w1 * s21;
        a[2] = w0 * s12 + w1 * s22;
        a[3] = w0 * c10 + w1 * c20;
        a[4] = w0 * c11 + w1 * c21;
        a[5] = w0 * c12 + w1 * c22;
        a[6]  = w0 * s10 * c10 + w1 * s20 * c20;
        a[7]  = w0 * s10 * c11 + w1 * s20 * c21;
        a[8]  = w0 * s10 * c12 + w1 * s20 * c22;
        a[9]  = w0 * s11 * c10 + w1 * s21 * c20;
        a[10] = w0 * s11 * c11 + w1 * s21 * c21;
        a[11] = w0 * s11 * c12 + w1 * s21 * c22;
        a[12] = w0 * s12 * c10 + w1 * s22 * c20;
        a[13] = w0 * s12 * c11 + w1 * s22 * c21;
        a[14] = w0 * s12 * c12 + w1 * s22 * c22;
    }
#pragma unroll
    for (int r = 0; r < 15; r++) {
        float val = a[r];
#pragma unroll
        for (int o = 16; o; o >>= 1) val += __shfl_xor_sync(~0u, val, o);
        if (lane == 0) red32[wid] = val;
        __syncthreads();
        if (wid == 0) {
            float v = red32[lane];
#pragma unroll
            for (int o = 16; o; o >>= 1) v += __shfl_xor_sync(~0u, v, o);
            if (lane == 0) g_res[b * 15 + r] = v;
        }
        __syncthreads();
    }

    for (int kk = 2; kk <= 2048; kk <<= 1) {
        for (int j = kk >> 1; j > 0; j >>= 1) {
            int i = t;
            int ixj = i ^ j;
            if (ixj > i) {
                float av = sv[i], bvv = sv[ixj];
                int ai = si[i], bi = si[ixj];
                bool aFirst = (av > bvv) || (av == bvv && ai < bi);
                bool desc = ((i & kk) == 0);
                if (desc != aFirst) {
                    sv[i] = bvv; si[i] = bi;
                    sv[ixj] = av; si[ixj] = ai;
                }
            }
            i = t + 1024;
            ixj = i ^ j;
            if (ixj > i) {
                float av = sv[i], bvv = sv[ixj];
                int ai = si[i], bi = si[ixj];
                bool aFirst = (av > bvv) || (av == bvv && ai < bi);
                bool desc = ((i & kk) == 0);
                if (desc != aFirst) {
                    sv[i] = bvv; si[i] = bi;
                    sv[ixj] = av; si[ixj] = ai;
                }
            }
            __syncthreads();
        }
    }
    g_topi[b * KEYv + t] = si[t];
}

// ---------------- fp32 3x3 Kabsch (downstream of topi; validated R10) -------
__device__ float det3f(const float M[3][3]) {
    return M[0][0] * (M[1][1] * M[2][2] - M[1][2] * M[2][1])
         - M[0][1] * (M[1][0] * M[2][2] - M[1][2] * M[2][0])
         + M[0][2] * (M[1][0] * M[2][1] - M[1][1] * M[2][0]);
}

__device__ void kabsch_Rf(const float H[3][3], float R[3][3]) {
    float A[3][3], V[3][3];
    for (int i = 0; i < 3; i++)
        for (int j = 0; j < 3; j++) {
            A[i][j] = H[0][i] * H[0][j] + H[1][i] * H[1][j] + H[2][i] * H[2][j];
            V[i][j] = (i == j) ? 1.0f : 0.0f;
        }
    for (int sweep = 0; sweep < 8; sweep++) {
        float off = fabsf(A[0][1]) + fabsf(A[0][2]) + fabsf(A[1][2]);
        if (off == 0.0f) break;
        const int PQ[3][2] = {{0, 1}, {0, 2}, {1, 2}};
        for (int pi = 0; pi < 3; pi++) {
            int p = PQ[pi][0], q = PQ[pi][1];
            float apq = A[p][q];
            if (fabsf(apq) < 1e-30f) continue;
            float app = A[p][p], aqq = A[q][q];
            float tau = (aqq - app) / (2.0f * apq);
            float tt = (tau >= 0.0f ? 1.0f : -1.0f) / (fabsf(tau) + sqrtf(1.0f + tau * tau));
            float cc = rsqrtf(1.0f + tt * tt);
            float ss = tt * cc;
            A[p][p] = app - tt * apq; A[q][q] = aqq + tt * apq;
            A[p][q] = 0.0f; A[q][p] = 0.0f;
            int r = 3 - p - q;
            float arp = A[r][p], arq = A[r][q];
            A[r][p] = cc * arp - ss * arq; A[p][r] = A[r][p];
            A[r][q] = ss * arp + cc * arq; A[q][r] = A[r][q];
            for (int i = 0; i < 3; i++) {
                float vp = V[i][p], vq = V[i][q];
                V[i][p] = cc * vp - ss * vq;
                V[i][q] = ss * vp + cc * vq;
            }
        }
    }
    float lam[3] = {A[0][0], A[1][1], A[2][2]};
    int ord[3] = {0, 1, 2};
    if (lam[ord[0]] < lam[ord[1]]) { int tmp = ord[0]; ord[0] = ord[1]; ord[1] = tmp; }
    if (lam[ord[0]] < lam[ord[2]]) { int tmp = ord[0]; ord[0] = ord[2]; ord[2] = tmp; }
    if (lam[ord[1]] < lam[ord[2]]) { int tmp = ord[1]; ord[1] = ord[2]; ord[2] = tmp; }
    float Vs[3][3], S[3], U[3][3];
    for (int k = 0; k < 3; k++) {
        int o = ord[k];
        S[k] = sqrtf(fmaxf(lam[o], 0.0f));
        for (int i = 0; i < 3; i++) Vs[i][k] = V[i][o];
    }
    for (int k = 0; k < 3; k++) {
        if (S[k] > 1e-20f) {
            float inv = 1.0f / S[k];
            for (int i = 0; i < 3; i++)
                U[i][k] = (H[i][0] * Vs[0][k] + H[i][1] * Vs[1][k] + H[i][2] * Vs[2][k]) * inv;
        } else {
            U[0][k] = U[1][0] * U[2][1] - U[2][0] * U[1][1];
            U[1][k] = U[2][0] * U[0][1] - U[0][0] * U[2][1];
            U[2][k] = U[0][0] * U[1][1] - U[1][0] * U[0][1];
        }
    }
    float d = det3f(U) * det3f(Vs);
    for (int i = 0; i < 3; i++)
        for (int j = 0; j < 3; j++)
            R[i][j] = Vs[i][0] * U[j][0] + Vs[i][1] * U[j][1] + d * Vs[i][2] * U[j][2];
}

// ---------------- SVD / rigid transform (fp32, 1 thread per batch) ----------
__global__ void k_svd(float* __restrict__ out) {
    int b = blockIdx.x;
    if (threadIdx.x != 0) return;
    if (b == 0) out[OFF_LOSS] = 0.f;     // zero loss accumulator for k_out
    const float* res = g_res + b * 15;
    float cs[3] = {res[0], res[1], res[2]};
    float ct[3] = {res[3], res[4], res[5]};
    float H[3][3];
    for (int i = 0; i < 3; i++)
        for (int j = 0; j < 3; j++)
            H[i][j] = res[6 + i * 3 + j] - cs[i] * ct[j];
    float R[3][3];
    kabsch_Rf(H, R);
    float tv[3];
    for (int i = 0; i < 3; i++)
        tv[i] = ct[i] - (R[i][0] * cs[0] + R[i][1] * cs[1] + R[i][2] * cs[2]);
    for (int i = 0; i < 3; i++)
        for (int j = 0; j < 3; j++) {
            out[OFF_R + b * 9 + i * 3 + j] = R[i][j];
            g_R[b * 9 + i * 3 + j] = R[i][j];
        }
    for (int i = 0; i < 3; i++) {
        out[OFF_T + b * 3 + i] = tv[i];
        g_tv[b * 3 + i] = tv[i];
    }
}

// ---------------- keypoint outputs (transform inline) + fused loss ----------
__global__ __launch_bounds__(256) void k_out(const float* __restrict__ src,
                                             const int* __restrict__ src_idx,
                                             float* __restrict__ out) {
    __shared__ float lred[8];
    int t = threadIdx.x;
    int gid = blockIdx.x * 256 + t;
    int k = gid & (Kv - 1);
    int jj = (gid >> 4) & (KEYv - 1);
    int b = gid >> 14;
    const float* R = g_R + b * 9;
    float R00 = R[0], R01 = R[1], R02 = R[2];
    float R10 = R[3], R11 = R[4], R12 = R[5];
    float R20 = R[6], R21 = R[7], R22 = R[8];
    int n = g_topi[b * KEYv + jj];
    int m = src_idx[((size_t)(b * Nv) + n) * Kv + k];
    const float* sb = src + (size_t)b * 3 * Nv;
    const float* cb = g_scorr + (size_t)b * 3 * Nv;
    float sn0 = sb[n], sn1 = sb[Nv + n], sn2 = sb[2 * Nv + n];
    float sm0 = sb[m], sm1 = sb[Nv + m], sm2 = sb[2 * Nv + m];
    float d0 = sn0 - sm0, d1 = sn1 - sm1, d2 = sn2 - sm2;
    float sk0 = R00 * d0 + R01 * d1 + R02 * d2;
    float sk1 = R10 * d0 + R11 * d1 + R12 * d2;
    float sk2 = R20 * d0 + R21 * d1 + R22 * d2;
    size_t o0 = ((size_t)(b * 3 + 0) * KEYv + jj) * Kv + k;
    size_t o1 = ((size_t)(b * 3 + 1) * KEYv + jj) * Kv + k;
    size_t o2 = ((size_t)(b * 3 + 2) * KEYv + jj) * Kv + k;
    out[OFF_SKK + o0] = sk0;
    out[OFF_SKK + o1] = sk1;
    out[OFF_SKK + o2] = sk2;
    float cn0 = cb[n], cn1 = cb[Nv + n], cn2 = cb[2 * Nv + n];
    out[OFF_TKK + o0] = cn0 - cb[m];
    out[OFF_TKK + o1] = cn1 - cb[Nv + m];
    out[OFF_TKK + o2] = cn2 - cb[2 * Nv + m];
    float lv = 0.f;
    if (k == 0) {
        out[OFF_SK + (size_t)(b * 3 + 0) * KEYv + jj] = sn0;
        out[OFF_SK + (size_t)(b * 3 + 1) * KEYv + jj] = sn1;
        out[OFF_SK + (size_t)(b * 3 + 2) * KEYv + jj] = sn2;
        out[OFF_TK + (size_t)(b * 3 + 0) * KEYv + jj] = cn0;
        out[OFF_TK + (size_t)(b * 3 + 1) * KEYv + jj] = cn1;
        out[OFF_TK + (size_t)(b * 3 + 2) * KEYv + jj] = cn2;
        lv = -__logf(g_maxp[(b << 11) + n] + 1e-15f);
    }
    int lane = t & 31, wid = t >> 5;
#pragma unroll
    for (int o = 16; o; o >>= 1) lv += __shfl_xor_sync(~0u, lv, o);
    if (lane == 0) lred[wid] = lv;
    __syncthreads();
    if (t == 0) {
        float s = 0.f;
#pragma unroll
        for (int j = 0; j < 8; j++) s += lred[j];
        atomicAdd(&out[OFF_LOSS], s * (1.0f / (Bv * KEYv)));
    }
}

// ---------------- launch -----------------------------------------------------
extern "C" void kernel_launch(void* const* d_in, const int* in_sizes, int n_in,
                              void* d_out, int out_size) {
    const float* src   = (const float*)d_in[0];
    const float* tgt   = (const float*)d_in[1];
    const float* semb  = (const float*)d_in[2];
    const float* temb  = (const float*)d_in[3];
    const float* sknn  = (const float*)d_in[4];
    const float* W1    = (const float*)d_in[6];
    const float* b1    = (const float*)d_in[7];
    const float* W2    = (const float*)d_in[8];
    const float* b2    = (const float*)d_in[9];
    const float* W3    = (const float*)d_in[10];
    const float* b3    = (const float*)d_in[11];
    const int*   sidx  = (const int*)d_in[12];
    const int*   sidx1 = (const int*)d_in[13];
    const int*   idx2  = (const int*)d_in[14];
    float* out = (float*)d_out;

    cudaFuncSetAttribute(k_mm, cudaFuncAttributeMaxDynamicSharedMemorySize, MM_SMEM);

    __nv_bfloat16* A2;
    __nv_bfloat16* B2;
    cudaGetSymbolAddress((void**)&A2, g_A2);
    cudaGetSymbolAddress((void**)&B2, g_B2);
    float* distp;
    cudaGetSymbolAddress((void**)&distp, g_dist);
    float* xxp;
    float* yyp;
    cudaGetSymbolAddress((void**)&xxp, g_xx);
    cudaGetSymbolAddress((void**)&yyp, g_yy);

    k_zero<<<16, 256>>>();
    dim3 cg(64, 16, 2);
    k_conv<<<cg, 256>>>(semb, A2, xxp);
    k_conv<<<cg, 256>>>(temb, B2, yyp);
    dim3 gg(Mv / 128, Nv / 128, Bv);
    k_mm<<<gg, 256, MM_SMEM>>>(distp);
    k_scores<<<Bv * Nv, 256>>>();
    k_rmm<<<Bv * Nv / 4, 256>>>(sidx1, idx2, tgt);
    k_disc<<<(Bv * Nv * Kv) / 256, 256>>>(src, sknn, sidx, W1, b1, W2, b2, W3, b3);
    k_post<<<Bv, 1024>>>(src);
    k_svd<<<Bv, 1>>>(out);
    k_out<<<(Bv * KEYv * Kv) / 256, 256>>>(src, sidx, out);
}

// round 13
// speedup vs baseline: 2.0774x; 1.0248x over previous
#include <cuda_runtime.h>
#include <cuda_bf16.h>
#include <math.h>
#include <stdint.h>

#define Bv   2
#define Nv   2048
#define Mv   2048
#define Cv   512
#define Kv   16
#define K1v  8
#define KEYv 1024
#define H1v  64
#define H2v  128

// d_out layout: R[2,3,3] | tvec[2,3] | src_kp[2,3,1024] | tgt_kp[2,3,1024]
//             | src_kp_knn[2,3,1024,16] | tgt_kp_knn[2,3,1024,16] | loss
#define OFF_R    0
#define OFF_T    18
#define OFF_SK   24
#define OFF_TK   (24 + 6144)
#define OFF_SKK  (24 + 12288)
#define OFF_TKK  (24 + 12288 + 98304)
#define OFF_LOSS (24 + 12288 + 196608)

// ---------------- scratch (device globals; no allocation allowed) -----------
__device__ float g_dist[Bv * Nv * Mv];   // 33.5 MB
__device__ float g_sc  [Bv * Nv * Mv];   // 33.5 MB  scores = softmax(-dist)
__device__ float g_xx[Bv * Nv];
__device__ float g_yy[Bv * Mv];
__device__ float g_z [Bv * Nv];
__device__ float g_scorr[Bv * 3 * Nv];
__device__ float g_maxp[Bv * Nv];
__device__ float g_s[Bv * Nv];
__device__ int   g_topi[Bv * KEYv];
__device__ float g_R[Bv * 9];
__device__ float g_tv[Bv * 3];
__device__ float g_res[Bv * 15];
// bf16 split embeddings, [b][n][0..511]=hi, [b][n][512..1023]=lo  (k-contig)
__device__ __align__(256) __nv_bfloat16 g_A2[Bv * Nv * 1024];
__device__ __align__(256) __nv_bfloat16 g_B2[Bv * Mv * 1024];

// =================== helpers ================================================
__device__ __forceinline__ uint32_t smem_to_u32(const void* p) {
    uint32_t a;
    asm("{ .reg .u64 t; cvta.to.shared.u64 t, %1; cvt.u32.u64 %0, t; }" : "=r"(a) : "l"(p));
    return a;
}
static __device__ __forceinline__ void cp_async16(uint32_t dst, const void* src) {
    asm volatile("cp.async.cg.shared.global [%0], [%1], 16;" :: "r"(dst), "l"(src) : "memory");
}
static __device__ __forceinline__ void ldm_x4(uint32_t* r, uint32_t addr) {
    asm volatile("ldmatrix.sync.aligned.m8n8.x4.shared.b16 {%0,%1,%2,%3}, [%4];"
                 : "=r"(r[0]), "=r"(r[1]), "=r"(r[2]), "=r"(r[3]) : "r"(addr));
}
static __device__ __forceinline__ void mma16816(float* c, const uint32_t* a,
                                                uint32_t b0, uint32_t b1) {
    asm volatile(
        "mma.sync.aligned.m16n8k16.row.col.f32.bf16.bf16.f32 "
        "{%0,%1,%2,%3},{%4,%5,%6,%7},{%8,%9},{%0,%1,%2,%3};"
        : "+f"(c[0]), "+f"(c[1]), "+f"(c[2]), "+f"(c[3])
        : "r"(a[0]), "r"(a[1]), "r"(a[2]), "r"(a[3]), "r"(b0), "r"(b1));
}

// ---------------- zero accumulators (FROZEN: round-7 upstream) --------------
__global__ void k_zero() {
    int i = blockIdx.x * 256 + threadIdx.x;
    g_xx[i] = 0.f;
    g_yy[i] = 0.f;
    g_z[i]  = 0.f;
}

// ------- fp32 -> bf16 hi/lo transpose-split + fused column sq-norms ---------
// FROZEN: round-7 upstream (summation order affects topi tie resolution).
__global__ __launch_bounds__(256) void k_conv(const float* __restrict__ e,
                                              __nv_bfloat16* __restrict__ out,
                                              float* __restrict__ norm) {
    __shared__ float ts[32][33];
    __shared__ float colsum[32];
    int b = blockIdx.z, c0 = blockIdx.y * 32, n0 = blockIdx.x * 32;
    int tx = threadIdx.x & 31, ty = threadIdx.x >> 5;
    if (threadIdx.x < 32) colsum[threadIdx.x] = 0.f;
    __syncthreads();
    float ps = 0.f;
    for (int i = ty; i < 32; i += 8) {
        float v = e[((size_t)b * Cv + c0 + i) * 2048 + n0 + tx];
        ts[i][tx] = v;
        ps = fmaf(v, v, ps);
    }
    atomicAdd(&colsum[tx], ps);
    __syncthreads();
    if (threadIdx.x < 32)
        atomicAdd(&norm[b * 2048 + n0 + threadIdx.x], colsum[threadIdx.x]);
    for (int i = ty; i < 32; i += 8) {
        float x = ts[tx][i];
        __nv_bfloat16 h = __float2bfloat16(x);
        __nv_bfloat16 l = __float2bfloat16(x - __bfloat162float(h));
        size_t base = ((size_t)b * 2048 + n0 + i) * 1024 + c0 + tx;
        out[base] = h;
        out[base + 512] = l;
    }
}

// ---------------- bf16 mma.sync GEMM: dist = xx - 2*A.B^T + yy --------------
// FROZEN: round-7/11 upstream SOURCE. CTA tile 128x128; K'=1536, 24 chunks.
#define MM_SMEM (6 * 16384)

__global__ __launch_bounds__(256) void k_mm(float* __restrict__ dist) {
    extern __shared__ char smem[];
    const uint32_t sbA = smem_to_u32(smem);            // 3 bufs x 128 rows x 128B
    const uint32_t sbB = sbA + 49152;                  // 3 bufs x 128 rows x 128B
    const int tid = threadIdx.x;
    const int lane = tid & 31, wid = tid >> 5;
    const int warp_m = (wid >> 1) * 32;
    const int warp_n = (wid & 1) * 64;
    const int bz = blockIdx.z;
    const int row0 = blockIdx.y * 128;
    const int col0 = blockIdx.x * 128;

    const char* Arow = (const char*)(g_A2 + ((size_t)bz * 2048 + row0) * 1024);
    const char* Brow = (const char*)(g_B2 + ((size_t)bz * 2048 + col0) * 1024);

    float c[2][8][4];
#pragma unroll
    for (int mt = 0; mt < 2; mt++)
#pragma unroll
        for (int nt = 0; nt < 8; nt++)
#pragma unroll
            for (int q = 0; q < 4; q++) c[mt][nt][q] = 0.f;

    auto load_chunk = [&](int it, int stage) {
        const int ab = ((it >= 16) ? 512 : 0) + (it & 7) * 64;
        const int bb = ((it >= 8 && it < 16) ? 512 : 0) + (it & 7) * 64;
        const char* ap = Arow + ab * 2;
        const char* bp = Brow + bb * 2;
        const uint32_t ad = sbA + stage * 16384;
        const uint32_t bd = sbB + stage * 16384;
#pragma unroll
        for (int u = 0; u < 4; u++) {
            int o = tid + u * 256;
            int r = o >> 3, s = o & 7;
            uint32_t sw = ((uint32_t)(s ^ (r & 7))) << 4;
            cp_async16(ad + r * 128 + sw, ap + (size_t)r * 2048 + s * 16);
            cp_async16(bd + r * 128 + sw, bp + (size_t)r * 2048 + s * 16);
        }
        asm volatile("cp.async.commit_group;" ::: "memory");
    };

    load_chunk(0, 0);
    load_chunk(1, 1);

    for (int it = 0; it < 24; it++) {
        if (it < 23) asm volatile("cp.async.wait_group 1;" ::: "memory");
        else         asm volatile("cp.async.wait_group 0;" ::: "memory");
        __syncthreads();
        if (it + 2 < 24) load_chunk(it + 2, (it + 2) % 3);

        const int buf = it % 3;
        const uint32_t aB = sbA + buf * 16384;
        const uint32_t bB = sbB + buf * 16384;
#pragma unroll
        for (int kk = 0; kk < 4; kk++) {
            uint32_t afr[2][4];
#pragma unroll
            for (int mt = 0; mt < 2; mt++) {
                int row = warp_m + mt * 16 + (lane & 7) + ((lane >> 3) & 1) * 8;
                int ch = 2 * kk + (lane >> 4);
                ldm_x4(afr[mt], aB + row * 128 + (((uint32_t)(ch ^ (row & 7))) << 4));
            }
            uint32_t bfr[4][4];
#pragma unroll
            for (int nt = 0; nt < 4; nt++) {
                int sel = lane >> 3;
                int row = warp_n + nt * 16 + (lane & 7) + (sel >> 1) * 8;
                int ch = 2 * kk + (sel & 1);
                ldm_x4(bfr[nt], bB + row * 128 + (((uint32_t)(ch ^ (row & 7))) << 4));
            }
#pragma unroll
            for (int mt = 0; mt < 2; mt++)
#pragma unroll
                for (int n8 = 0; n8 < 8; n8++)
                    mma16816(c[mt][n8], afr[mt],
                             bfr[n8 >> 1][(n8 & 1) * 2], bfr[n8 >> 1][(n8 & 1) * 2 + 1]);
        }
    }

    const int grp = lane >> 2, qp = lane & 3;
#pragma unroll
    for (int mt = 0; mt < 2; mt++) {
        int m = warp_m + mt * 16 + grp;
        float x0 = g_xx[bz * 2048 + row0 + m];
        float x1 = g_xx[bz * 2048 + row0 + m + 8];
        float* d0 = dist + ((size_t)(bz * 2048 + row0 + m)) * 2048 + col0;
        float* d1 = d0 + (size_t)8 * 2048;
#pragma unroll
        for (int n8 = 0; n8 < 8; n8++) {
            int n = warp_n + n8 * 8 + qp * 2;
            float y0 = g_yy[bz * 2048 + col0 + n];
            float y1 = g_yy[bz * 2048 + col0 + n + 1];
            float2 v0, v1;
            v0.x = fmaf(-2.f, c[mt][n8][0], x0 + y0);
            v0.y = fmaf(-2.f, c[mt][n8][1], x0 + y1);
            v1.x = fmaf(-2.f, c[mt][n8][2], x1 + y0);
            v1.y = fmaf(-2.f, c[mt][n8][3], x1 + y1);
            *(float2*)(d0 + n) = v0;
            *(float2*)(d1 + n) = v1;
        }
    }
}

// ---------------- scores = softmax(-dist) row-wise (FROZEN) -----------------
__global__ __launch_bounds__(256) void k_scores() {
    int row = blockIdx.x;
    const float4* d = (const float4*)(g_dist + (size_t)row * Mv);
    float4* sc = (float4*)(g_sc + (size_t)row * Mv);
    __shared__ float red[8];
    __shared__ float bc;
    int t = threadIdx.x, lane = t & 31, wid = t >> 5;
    float4 v0 = d[t], v1 = d[t + 256];
    float4 e0, e1;
    e0.x = __expf(-v0.x); e0.y = __expf(-v0.y); e0.z = __expf(-v0.z); e0.w = __expf(-v0.w);
    e1.x = __expf(-v1.x); e1.y = __expf(-v1.y); e1.z = __expf(-v1.z); e1.w = __expf(-v1.w);
    float zs = (e0.x + e0.y) + (e0.z + e0.w) + (e1.x + e1.y) + (e1.z + e1.w);
#pragma unroll
    for (int o = 16; o; o >>= 1) zs += __shfl_xor_sync(~0u, zs, o);
    if (lane == 0) red[wid] = zs;
    __syncthreads();
    if (t == 0) {
        float z = 0.f;
#pragma unroll
        for (int i = 0; i < 8; i++) z += red[i];
        bc = 1.0f / z;
    }
    __syncthreads();
    float iz = bc;
    e0.x *= iz; e0.y *= iz; e0.z *= iz; e0.w *= iz;
    e1.x *= iz; e1.y *= iz; e1.z *= iz; e1.w *= iz;
    sc[t] = e0;
    sc[t + 256] = e1;
}

// -------- fused k_rmm: 4 rows/block, single sweep (FROZEN) ------------------
__global__ __launch_bounds__(256) void k_rmm(const int* __restrict__ idx1,
                                             const int* __restrict__ idx2,
                                             const float* __restrict__ tgt) {
    __shared__ float Trow[4][2048];
    __shared__ float redA[20][8];
    __shared__ float bc[4];
    int blk = blockIdx.x;
    int b = blk >> 9;
    int n0 = (blk & 511) * 4;
    int t = threadIdx.x, lane = t & 31, wid = t >> 5;

    const float4* base = (const float4*)(g_sc + (size_t)(b << 11) * Mv);
#pragma unroll
    for (int r = 0; r < 4; r++) {
        const int* ip = idx1 + (size_t)((b << 11) + n0 + r) * K1v;
        const float4* r0 = base + (size_t)ip[1] * 512;
        const float4* r1 = base + (size_t)ip[2] * 512;
        const float4* r2 = base + (size_t)ip[3] * 512;
        const float4* r3 = base + (size_t)ip[4] * 512;
        const float4* r4 = base + (size_t)ip[5] * 512;
        const float4* r5 = base + (size_t)ip[6] * 512;
        const float4* r6 = base + (size_t)ip[7] * 512;
        float4* Tv = (float4*)Trow[r];
        for (int q = t; q < 512; q += 256) {
            float4 a0 = r0[q], a1 = r1[q], a2 = r2[q], a3 = r3[q];
            float4 a4 = r4[q], a5 = r5[q], a6 = r6[q];
            float4 o;
            o.x = ((a0.x + a1.x) + (a2.x + a3.x)) + ((a4.x + a5.x) + a6.x);
            o.y = ((a0.y + a1.y) + (a2.y + a3.y)) + ((a4.y + a5.y) + a6.y);
            o.z = ((a0.z + a1.z) + (a2.z + a3.z)) + ((a4.z + a5.z) + a6.z);
            o.w = ((a0.w + a1.w) + (a2.w + a3.w)) + ((a4.w + a5.w) + a6.w);
            Tv[q] = o;
        }
    }
    __syncthreads();

    const float* dp0 = g_dist + (size_t)((b << 11) + n0) * Mv;
    const int4* i2 = (const int4*)(idx2 + (size_t)b * Mv * K1v);
    const float* t0 = tgt + (size_t)b * 3 * Mv;
    float zs[4] = {0.f, 0.f, 0.f, 0.f};
    float em[4] = {0.f, 0.f, 0.f, 0.f};
    float acc[12];
#pragma unroll
    for (int i = 0; i < 12; i++) acc[i] = 0.f;
    for (int m = t; m < Mv; m += 256) {
        int4 lo = i2[m * 2], hi = i2[m * 2 + 1];
        float v0 = t0[m], v1 = t0[Mv + m], v2 = t0[2 * Mv + m];
#pragma unroll
        for (int r = 0; r < 4; r++) {
            const float* T = Trow[r];
            float S = T[lo.y] + T[lo.z] + T[lo.w] +
                      T[hi.x] + T[hi.y] + T[hi.z] + T[hi.w];
            float wq = __expf(1.0f - S * (1.0f / 7.0f));
            float e = __expf(-wq * dp0[(size_t)r * Mv + m]);
            zs[r] += e;
            em[r] = fmaxf(em[r], e);
            acc[r * 3 + 0] = fmaf(v0, e, acc[r * 3 + 0]);
            acc[r * 3 + 1] = fmaf(v1, e, acc[r * 3 + 1]);
            acc[r * 3 + 2] = fmaf(v2, e, acc[r * 3 + 2]);
        }
    }

#pragma unroll
    for (int r = 0; r < 4; r++) {
        float z = zs[r], mx = em[r];
#pragma unroll
        for (int o = 16; o; o >>= 1) {
            z += __shfl_xor_sync(~0u, z, o);
            mx = fmaxf(mx, __shfl_xor_sync(~0u, mx, o));
        }
        if (lane == 0) { redA[r][wid] = z; redA[4 + r][wid] = mx; }
    }
#pragma unroll
    for (int i = 0; i < 12; i++) {
        float v = acc[i];
#pragma unroll
        for (int o = 16; o; o >>= 1) v += __shfl_xor_sync(~0u, v, o);
        if (lane == 0) redA[8 + i][wid] = v;
    }
    __syncthreads();
    if (t < 4) {
        float z = 0.f;
#pragma unroll
        for (int j = 0; j < 8; j++) z += redA[t][j];
        bc[t] = 1.0f / z;
    }
    __syncthreads();
    if (t >= 4 && t < 8) {
        int r = t - 4;
        float mx = 0.f;
#pragma unroll
        for (int j = 0; j < 8; j++) mx = fmaxf(mx, redA[t][j]);
        g_maxp[(b << 11) + n0 + r] = mx * bc[r];
    } else if (t >= 8 && t < 20) {
        int i = t - 8;
        float s = 0.f;
#pragma unroll
        for (int j = 0; j < 8; j++) s += redA[t][j];
        int r = i / 3, cc = i % 3;
        g_scorr[(b * 3 + cc) * Nv + n0 + r] = s * bc[r];
    }
}

// ---------------- discriminator MLP + max over k (FROZEN) -------------------
__global__ __launch_bounds__(256) void k_disc(const float* __restrict__ src,
                                              const float* __restrict__ src_knn,
                                              const int* __restrict__ src_idx,
                                              const float* __restrict__ W1, const float* __restrict__ b1,
                                              const float* __restrict__ W2, const float* __restrict__ b2,
                                              const float* __restrict__ W3, const float* __restrict__ b3) {
    __shared__ float sW1[H1v * 6], sb1[H1v], sW2[H2v * H1v], sb2[H2v], sW3[H2v];
    __shared__ float sb3s;
    int t = threadIdx.x;
    for (int i = t; i < H1v * 6; i += 256) sW1[i] = W1[i];
    for (int i = t; i < H1v; i += 256) sb1[i] = b1[i];
    for (int i = t; i < H2v * H1v; i += 256) sW2[i] = W2[i];
    for (int i = t; i < H2v; i += 256) { sb2[i] = b2[i]; sW3[i] = W3[i]; }
    if (t == 0) sb3s = b3[0];
    __syncthreads();

    int gid = blockIdx.x * 256 + t;
    int k = gid & (Kv - 1);
    int n = (gid >> 4) & (Nv - 1);
    int b = gid >> 15;
    int j = src_idx[(size_t)gid];
    float f[6];
#pragma unroll
    for (int c = 0; c < 3; c++) {
        f[c]     = g_scorr[(b * 3 + c) * Nv + n] - g_scorr[(b * 3 + c) * Nv + j];
        f[3 + c] = src[(size_t)(b * 3 + c) * Nv + n] - src_knn[(size_t)gid * 3 + c];
    }
    float h1[H1v];
#pragma unroll
    for (int d = 0; d < H1v; d++) {
        float a = sb1[d];
#pragma unroll
        for (int c = 0; c < 6; c++) a = fmaf(sW1[d * 6 + c], f[c], a);
        h1[d] = fmaxf(a, 0.f);
    }
    float s = sb3s;
    const float4* W2v = (const float4*)sW2;
    for (int e = 0; e < H2v; e++) {
        float a = sb2[e];
#pragma unroll
        for (int dq = 0; dq < 16; dq++) {
            float4 w = W2v[e * 16 + dq];
            a = fmaf(w.x, h1[dq * 4 + 0], a);
            a = fmaf(w.y, h1[dq * 4 + 1], a);
            a = fmaf(w.z, h1[dq * 4 + 2], a);
            a = fmaf(w.w, h1[dq * 4 + 3], a);
        }
        s = fmaf(sW3[e], fmaxf(a, 0.f), s);
    }
#pragma unroll
    for (int off = 8; off > 0; off >>= 1)
        s = fmaxf(s, __shfl_xor_sync(0xffffffffu, s, off, 16));
    if (k == 0) g_s[(b << 11) + n] = s;
}

// ------- fused: weight softmax + rigid sums + exact top-k (FROZEN) ----------
__global__ __launch_bounds__(1024) void k_post(const float* __restrict__ src) {
    int b = blockIdx.x; int t = threadIdx.x;
    int lane = t & 31, wid = t >> 5;
    __shared__ float sv[2048];
    __shared__ int   si[2048];
    __shared__ float red32[32];
    __shared__ float bcast;
    const float* s = g_s + b * Nv;
    float v0 = s[t], v1 = s[t + 1024];
    float mx = fmaxf(v0, v1);
#pragma unroll
    for (int o = 16; o; o >>= 1) mx = fmaxf(mx, __shfl_xor_sync(~0u, mx, o));
    if (lane == 0) red32[wid] = mx;
    __syncthreads();
    if (wid == 0) {
        float m = red32[lane];
#pragma unroll
        for (int o = 16; o; o >>= 1) m = fmaxf(m, __shfl_xor_sync(~0u, m, o));
        if (lane == 0) bcast = m;
    }
    __syncthreads();
    mx = bcast;
    float e0 = __expf(v0 - mx), e1 = __expf(v1 - mx);
    float zs = e0 + e1;
#pragma unroll
    for (int o = 16; o; o >>= 1) zs += __shfl_xor_sync(~0u, zs, o);
    if (lane == 0) red32[wid] = zs;
    __syncthreads();
    if (wid == 0) {
        float z = red32[lane];
#pragma unroll
        for (int o = 16; o; o >>= 1) z += __shfl_xor_sync(~0u, z, o);
        if (lane == 0) bcast = z;
    }
    __syncthreads();
    float inv = 1.0f / bcast;
    float w0 = e0 * inv, w1 = e1 * inv;
    sv[t] = w0;          si[t] = t;
    sv[t + 1024] = w1;   si[t + 1024] = t + 1024;

    const float* sx = src + (size_t)b * 3 * Nv;
    const float* cx = g_scorr + (size_t)b * 3 * Nv;
    float a[15];
    {
        int n1 = t, n2 = t + 1024;
        float s10 = sx[n1], s11 = sx[Nv + n1], s12 = sx[2 * Nv + n1];
        float c10 = cx[n1], c11 = cx[Nv + n1], c12 = cx[2 * Nv + n1];
        float s20 = sx[n2], s21 = sx[Nv + n2], s22 = sx[2 * Nv + n2];
        float c20 = cx[n2], c21 = cx[Nv + n2], c22 = cx[2 * Nv + n2];
        a[0] = w0 * s10 + w1 * s20;
        a[1] = w0 * s11 + w1 * s21;
        a[2] = w0 * s12 + w1 * s22;
        a[3] = w0 * c10 + w1 * c20;
        a[4] = w0 * c11 + w1 * c21;
        a[5] = w0 * c12 + w1 * c22;
        a[6]  = w0 * s10 * c10 + w1 * s20 * c20;
        a[7]  = w0 * s10 * c11 + w1 * s20 * c21;
        a[8]  = w0 * s10 * c12 + w1 * s20 * c22;
        a[9]  = w0 * s11 * c10 + w1 * s21 * c20;
        a[10] = w0 * s11 * c11 + w1 * s21 * c21;
        a[11] = w0 * s11 * c12 + w1 * s21 * c22;
        a[12] = w0 * s12 * c10 + w1 * s22 * c20;
        a[13] = w0 * s12 * c11 + w1 * s22 * c21;
        a[14] = w0 * s12 * c12 + w1 * s22 * c22;
    }
#pragma unroll
    for (int r = 0; r < 15; r++) {
        float val = a[r];
#pragma unroll
        for (int o = 16; o; o >>= 1) val += __shfl_xor_sync(~0u, val, o);
        if (lane == 0) red32[wid] = val;
        __syncthreads();
        if (wid == 0) {
            float v = red32[lane];
#pragma unroll
            for (int o = 16; o; o >>= 1) v += __shfl_xor_sync(~0u, v, o);
            if (lane == 0) g_res[b * 15 + r] = v;
        }
        __syncthreads();
    }

    for (int kk = 2; kk <= 2048; kk <<= 1) {
        for (int j = kk >> 1; j > 0; j >>= 1) {
            int i = t;
            int ixj = i ^ j;
            if (ixj > i) {
                float av = sv[i], bvv = sv[ixj];
                int ai = si[i], bi = si[ixj];
                bool aFirst = (av > bvv) || (av == bvv && ai < bi);
                bool desc = ((i & kk) == 0);
                if (desc != aFirst) {
                    sv[i] = bvv; si[i] = bi;
                    sv[ixj] = av; si[ixj] = ai;
                }
            }
            i = t + 1024;
            ixj = i ^ j;
            if (ixj > i) {
                float av = sv[i], bvv = sv[ixj];
                int ai = si[i], bi = si[ixj];
                bool aFirst = (av > bvv) || (av == bvv && ai < bi);
                bool desc = ((i & kk) == 0);
                if (desc != aFirst) {
                    sv[i] = bvv; si[i] = bi;
                    sv[ixj] = av; si[ixj] = ai;
                }
            }
            __syncthreads();
        }
    }
    g_topi[b * KEYv + t] = si[t];
}

// ---------------- fp32 3x3 Kabsch (downstream of topi; validated R10/R11) ---
__device__ float det3f(const float M[3][3]) {
    return M[0][0] * (M[1][1] * M[2][2] - M[1][2] * M[2][1])
         - M[0][1] * (M[1][0] * M[2][2] - M[1][2] * M[2][0])
         + M[0][2] * (M[1][0] * M[2][1] - M[1][1] * M[2][0]);
}

__device__ void kabsch_Rf(const float H[3][3], float R[3][3]) {
    float A[3][3], V[3][3];
    for (int i = 0; i < 3; i++)
        for (int j = 0; j < 3; j++) {
            A[i][j] = H[0][i] * H[0][j] + H[1][i] * H[1][j] + H[2][i] * H[2][j];
            V[i][j] = (i == j) ? 1.0f : 0.0f;
        }
    for (int sweep = 0; sweep < 8; sweep++) {
        float off = fabsf(A[0][1]) + fabsf(A[0][2]) + fabsf(A[1][2]);
        if (off == 0.0f) break;
        const int PQ[3][2] = {{0, 1}, {0, 2}, {1, 2}};
        for (int pi = 0; pi < 3; pi++) {
            int p = PQ[pi][0], q = PQ[pi][1];
            float apq = A[p][q];
            if (fabsf(apq) < 1e-30f) continue;
            float app = A[p][p], aqq = A[q][q];
            float tau = (aqq - app) / (2.0f * apq);
            float tt = (tau >= 0.0f ? 1.0f : -1.0f) / (fabsf(tau) + sqrtf(1.0f + tau * tau));
            float cc = rsqrtf(1.0f + tt * tt);
            float ss = tt * cc;
            A[p][p] = app - tt * apq; A[q][q] = aqq + tt * apq;
            A[p][q] = 0.0f; A[q][p] = 0.0f;
            int r = 3 - p - q;
            float arp = A[r][p], arq = A[r][q];
            A[r][p] = cc * arp - ss * arq; A[p][r] = A[r][p];
            A[r][q] = ss * arp + cc * arq; A[q][r] = A[r][q];
            for (int i = 0; i < 3; i++) {
                float vp = V[i][p], vq = V[i][q];
                V[i][p] = cc * vp - ss * vq;
                V[i][q] = ss * vp + cc * vq;
            }
        }
    }
    float lam[3] = {A[0][0], A[1][1], A[2][2]};
    int ord[3] = {0, 1, 2};
    if (lam[ord[0]] < lam[ord[1]]) { int tmp = ord[0]; ord[0] = ord[1]; ord[1] = tmp; }
    if (lam[ord[0]] < lam[ord[2]]) { int tmp = ord[0]; ord[0] = ord[2]; ord[2] = tmp; }
    if (lam[ord[1]] < lam[ord[2]]) { int tmp = ord[1]; ord[1] = ord[2]; ord[2] = tmp; }
    float Vs[3][3], S[3], U[3][3];
    for (int k = 0; k < 3; k++) {
        int o = ord[k];
        S[k] = sqrtf(fmaxf(lam[o], 0.0f));
        for (int i = 0; i < 3; i++) Vs[i][k] = V[i][o];
    }
    for (int k = 0; k < 3; k++) {
        if (S[k] > 1e-20f) {
            float inv = 1.0f / S[k];
            for (int i = 0; i < 3; i++)
                U[i][k] = (H[i][0] * Vs[0][k] + H[i][1] * Vs[1][k] + H[i][2] * Vs[2][k]) * inv;
        } else {
            U[0][k] = U[1][0] * U[2][1] - U[2][0] * U[1][1];
            U[1][k] = U[2][0] * U[0][1] - U[0][0] * U[2][1];
            U[2][k] = U[0][0] * U[1][1] - U[1][0] * U[0][1];
        }
    }
    float d = det3f(U) * det3f(Vs);
    for (int i = 0; i < 3; i++)
        for (int j = 0; j < 3; j++)
            R[i][j] = Vs[i][0] * U[j][0] + Vs[i][1] * U[j][1] + d * Vs[i][2] * U[j][2];
}

// ---------------- SVD / rigid transform (fp32, 1 thread per batch) ----------
__global__ void k_svd(float* __restrict__ out) {
    int b = blockIdx.x;
    if (threadIdx.x != 0) return;
    if (b == 0) out[OFF_LOSS] = 0.f;     // zero loss accumulator for k_out
    const float* res = g_res + b * 15;
    float cs[3] = {res[0], res[1], res[2]};
    float ct[3] = {res[3], res[4], res[5]};
    float H[3][3];
    for (int i = 0; i < 3; i++)
        for (int j = 0; j < 3; j++)
            H[i][j] = res[6 + i * 3 + j] - cs[i] * ct[j];
    float R[3][3];
    kabsch_Rf(H, R);
    float tv[3];
    for (int i = 0; i < 3; i++)
        tv[i] = ct[i] - (R[i][0] * cs[0] + R[i][1] * cs[1] + R[i][2] * cs[2]);
    for (int i = 0; i < 3; i++)
        for (int j = 0; j < 3; j++) {
            out[OFF_R + b * 9 + i * 3 + j] = R[i][j];
            g_R[b * 9 + i * 3 + j] = R[i][j];
        }
    for (int i = 0; i < 3; i++) {
        out[OFF_T + b * 3 + i] = tv[i];
        g_tv[b * 3 + i] = tv[i];
    }
}

// ---------------- keypoint outputs (transform inline) + fused loss ----------
__global__ __launch_bounds__(256) void k_out(const float* __restrict__ src,
                                             const int* __restrict__ src_idx,
                                             float* __restrict__ out) {
    __shared__ float lred[8];
    int t = threadIdx.x;
    int gid = blockIdx.x * 256 + t;
    int k = gid & (Kv - 1);
    int jj = (gid >> 4) & (KEYv - 1);
    int b = gid >> 14;
    const float* R = g_R + b * 9;
    float R00 = R[0], R01 = R[1], R02 = R[2];
    float R10 = R[3], R11 = R[4], R12 = R[5];
    float R20 = R[6], R21 = R[7], R22 = R[8];
    int n = g_topi[b * KEYv + jj];
    int m = src_idx[((size_t)(b * Nv) + n) * Kv + k];
    const float* sb = src + (size_t)b * 3 * Nv;
    const float* cb = g_scorr + (size_t)b * 3 * Nv;
    float sn0 = sb[n], sn1 = sb[Nv + n], sn2 = sb[2 * Nv + n];
    float sm0 = sb[m], sm1 = sb[Nv + m], sm2 = sb[2 * Nv + m];
    float d0 = sn0 - sm0, d1 = sn1 - sm1, d2 = sn2 - sm2;
    float sk0 = R00 * d0 + R01 * d1 + R02 * d2;
    float sk1 = R10 * d0 + R11 * d1 + R12 * d2;
    float sk2 = R20 * d0 + R21 * d1 + R22 * d2;
    size_t o0 = ((size_t)(b * 3 + 0) * KEYv + jj) * Kv + k;
    size_t o1 = ((size_t)(b * 3 + 1) * KEYv + jj) * Kv + k;
    size_t o2 = ((size_t)(b * 3 + 2) * KEYv + jj) * Kv + k;
    out[OFF_SKK + o0] = sk0;
    out[OFF_SKK + o1] = sk1;
    out[OFF_SKK + o2] = sk2;
    float cn0 = cb[n], cn1 = cb[Nv + n], cn2 = cb[2 * Nv + n];
    out[OFF_TKK + o0] = cn0 - cb[m];
    out[OFF_TKK + o1] = cn1 - cb[Nv + m];
    out[OFF_TKK + o2] = cn2 - cb[2 * Nv + m];
    float lv = 0.f;
    if (k == 0) {
        out[OFF_SK + (size_t)(b * 3 + 0) * KEYv + jj] = sn0;
        out[OFF_SK + (size_t)(b * 3 + 1) * KEYv + jj] = sn1;
        out[OFF_SK + (size_t)(b * 3 + 2) * KEYv + jj] = sn2;
        out[OFF_TK + (size_t)(b * 3 + 0) * KEYv + jj] = cn0;
        out[OFF_TK + (size_t)(b * 3 + 1) * KEYv + jj] = cn1;
        out[OFF_TK + (size_t)(b * 3 + 2) * KEYv + jj] = cn2;
        lv = -__logf(g_maxp[(b << 11) + n] + 1e-15f);
    }
    int lane = t & 31, wid = t >> 5;
#pragma unroll
    for (int o = 16; o; o >>= 1) lv += __shfl_xor_sync(~0u, lv, o);
    if (lane == 0) lred[wid] = lv;
    __syncthreads();
    if (t == 0) {
        float s = 0.f;
#pragma unroll
        for (int j = 0; j < 8; j++) s += lred[j];
        atomicAdd(&out[OFF_LOSS], s * (1.0f / (Bv * KEYv)));
    }
}

// ---------------- launch -----------------------------------------------------
extern "C" void kernel_launch(void* const* d_in, const int* in_sizes, int n_in,
                              void* d_out, int out_size) {
    const float* src   = (const float*)d_in[0];
    const float* tgt   = (const float*)d_in[1];
    const float* semb  = (const float*)d_in[2];
    const float* temb  = (const float*)d_in[3];
    const float* sknn  = (const float*)d_in[4];
    const float* W1    = (const float*)d_in[6];
    const float* b1    = (const float*)d_in[7];
    const float* W2    = (const float*)d_in[8];
    const float* b2    = (const float*)d_in[9];
    const float* W3    = (const float*)d_in[10];
    const float* b3    = (const float*)d_in[11];
    const int*   sidx  = (const int*)d_in[12];
    const int*   sidx1 = (const int*)d_in[13];
    const int*   idx2  = (const int*)d_in[14];
    float* out = (float*)d_out;

    cudaFuncSetAttribute(k_mm, cudaFuncAttributeMaxDynamicSharedMemorySize, MM_SMEM);

    __nv_bfloat16* A2;
    __nv_bfloat16* B2;
    cudaGetSymbolAddress((void**)&A2, g_A2);
    cudaGetSymbolAddress((void**)&B2, g_B2);
    float* distp;
    cudaGetSymbolAddress((void**)&distp, g_dist);
    float* xxp;
    float* yyp;
    cudaGetSymbolAddress((void**)&xxp, g_xx);
    cudaGetSymbolAddress((void**)&yyp, g_yy);

    k_zero<<<16, 256>>>();
    dim3 cg(64, 16, 2);
    k_conv<<<cg, 256>>>(semb, A2, xxp);
    k_conv<<<cg, 256>>>(temb, B2, yyp);
    dim3 gg(Mv / 128, Nv / 128, Bv);
    k_mm<<<gg, 256, MM_SMEM>>>(distp);
    k_scores<<<Bv * Nv, 256>>>();
    k_rmm<<<Bv * Nv / 4, 256>>>(sidx1, idx2, tgt);
    k_disc<<<(Bv * Nv * Kv) / 256, 256>>>(src, sknn, sidx, W1, b1, W2, b2, W3, b3);
    k_post<<<Bv, 1024>>>(src);
    k_svd<<<Bv, 1>>>(out);
    k_out<<<(Bv * KEYv * Kv) / 256, 256>>>(src, sidx, out);
}